// round 4
// baseline (speedup 1.0000x reference)
#include <cuda_runtime.h>
#include <math.h>

// Problem constants (fixed by the reference)
#define BB   64
#define SS   128
#define HH   1024
#define EE   1024
#define EMBD 512
#define VV   32000
#define TT   50
#define KCAT 1536          // EMBD + HH (concat of prev-embedding and h)
#define NGATE 4096         // 4*HH

// ---------------------------------------------------------------------------
// Device scratch (static device globals — no allocation)
// ---------------------------------------------------------------------------
__device__ float g_keys[(size_t)BB * SS * HH];   // att keys [B,S,H]  (33.5 MB)
__device__ float g_wcat[(size_t)NGATE * KCAT];   // [W_ih | W_hh]     (25 MB)
__device__ float g_xcat[BB * KCAT];              // [prev_emb | h] per batch row
__device__ float g_hc[BB * 2048];                // [h | c_t] per batch row
__device__ float g_c[BB * HH];                   // LSTM cell state
__device__ float g_gates[BB * NGATE];            // LSTM pre-activations
__device__ float g_dec[BB * EMBD];               // out-projection result

// ---------------------------------------------------------------------------
// Generic tiled SGEMM:  C[M,N] = A[M,K] * B[N,K]^T  (+ bias[N])
// 256 threads, TM=64, TK=16, TN in {16,32,64}; thread tile = 4 x (TN/16).
// Requires: M % 64 == 0 handled by grid (M<=64 OK via exact sizes),
//           N % TN == 0, K % 16 == 0 (all shapes here satisfy this).
// ---------------------------------------------------------------------------
template<int TN>
__global__ void __launch_bounds__(256)
sgemm_abt(const float* __restrict__ A, int lda,
          const float* __restrict__ B, int ldb,
          float* __restrict__ C, size_t ldc,
          int M, int N, int K,
          const float* __restrict__ bias)
{
    constexpr int TM  = 64;
    constexpr int TK  = 16;
    constexpr int TRN = TN / 16;               // columns per thread
    __shared__ float As[TK][TM + 4];
    __shared__ float Bs[TK][TN + 4];

    const int tid = threadIdx.x;               // 0..255
    const int tx  = tid & 15;                  // column group
    const int ty  = tid >> 4;                  // row group (0..15) * 4 rows
    const int m0  = blockIdx.y * TM;
    const int n0  = blockIdx.x * TN;

    float acc[4][TRN];
#pragma unroll
    for (int i = 0; i < 4; i++)
#pragma unroll
        for (int j = 0; j < TRN; j++) acc[i][j] = 0.f;

    const int lc = tid & 15;                   // k within chunk
    const int lr = tid >> 4;                   // base row

    for (int k0 = 0; k0 < K; k0 += TK) {
#pragma unroll
        for (int i = 0; i < 4; i++) {          // A tile: 64x16
            int r = lr + 16 * i;
            As[lc][r] = A[(size_t)(m0 + r) * lda + (k0 + lc)];
        }
#pragma unroll
        for (int i = 0; i < (TN * TK) / 256; i++) {  // B tile: TNx16
            int r = lr + 16 * i;
            Bs[lc][r] = B[(size_t)(n0 + r) * ldb + (k0 + lc)];
        }
        __syncthreads();
#pragma unroll
        for (int kk = 0; kk < TK; kk++) {
            float a[4], b[TRN];
#pragma unroll
            for (int i = 0; i < 4; i++)   a[i] = As[kk][ty * 4 + i];
#pragma unroll
            for (int j = 0; j < TRN; j++) b[j] = Bs[kk][tx * TRN + j];
#pragma unroll
            for (int i = 0; i < 4; i++)
#pragma unroll
                for (int j = 0; j < TRN; j++)
                    acc[i][j] = fmaf(a[i], b[j], acc[i][j]);
        }
        __syncthreads();
    }

#pragma unroll
    for (int i = 0; i < 4; i++) {
        int m = m0 + ty * 4 + i;
        if (m >= M) continue;
#pragma unroll
        for (int j = 0; j < TRN; j++) {
            int n = n0 + tx * TRN + j;
            float v = acc[i][j];
            if (bias) v += bias[n];
            C[(size_t)m * ldc + n] = v;
        }
    }
}

// ---------------------------------------------------------------------------
// Setup kernels
// ---------------------------------------------------------------------------
__global__ void build_wcat(const float* __restrict__ W_ih,
                           const float* __restrict__ W_hh)
{
    size_t total = (size_t)NGATE * KCAT;
    for (size_t i = (size_t)blockIdx.x * blockDim.x + threadIdx.x; i < total;
         i += (size_t)gridDim.x * blockDim.x) {
        int j = (int)(i / KCAT);
        int k = (int)(i % KCAT);
        g_wcat[i] = (k < EMBD) ? W_ih[(size_t)j * EMBD + k]
                               : W_hh[(size_t)j * HH + (k - EMBD)];
    }
}

__global__ void init_state(const float* __restrict__ dec_init)
{
    int idx = blockIdx.x * blockDim.x + threadIdx.x;   // 65536 = B*H
    int b = idx >> 10, j = idx & 1023;
    float h0 = dec_init[idx];                          // [0,0,b,j]
    g_hc[b * 2048 + j] = h0;
    g_xcat[b * KCAT + EMBD + j] = h0;
    g_c[idx] = dec_init[BB * HH + idx];                // [1,0,b,j]
    if (j < EMBD) g_xcat[b * KCAT + j] = 0.f;          // prev0 = 0
}

// ---------------------------------------------------------------------------
// LSTM cell elementwise
// ---------------------------------------------------------------------------
__device__ __forceinline__ float sigf(float x) { return 1.f / (1.f + expf(-x)); }

__global__ void lstm_cell()
{
    int idx = blockIdx.x * blockDim.x + threadIdx.x;   // B*H
    int b = idx >> 10, j = idx & 1023;
    const float* g = &g_gates[b * NGATE];
    float ig = g[j], fg = g[1024 + j], gg = g[2048 + j], og = g[3072 + j];
    float c = sigf(fg) * g_c[idx] + sigf(ig) * tanhf(gg);
    float h = sigf(og) * tanhf(c);
    g_c[idx] = c;
    g_hc[b * 2048 + j] = h;
    g_xcat[b * KCAT + EMBD + j] = h;
}

// ---------------------------------------------------------------------------
// Attention: scores -> masked softmax -> context, one block per batch row
// ---------------------------------------------------------------------------
__global__ void __launch_bounds__(256)
attention(const float* __restrict__ enc, const int* __restrict__ enc_len)
{
    int b = blockIdx.x;
    int tid = threadIdx.x;
    int warp = tid >> 5, lane = tid & 31;

    __shared__ float sh[HH];
    __shared__ float sa[SS];
    __shared__ float red[8];
    __shared__ float bc;

    for (int i = tid; i < HH; i += 256) sh[i] = g_hc[b * 2048 + i];
    __syncthreads();

    // scores[s] = keys[b,s,:] . h   (8 warps x 16 scores)
    for (int si = 0; si < 16; si++) {
        int s = warp * 16 + si;
        const float* kr = &g_keys[((size_t)b * SS + s) * HH];
        float acc = 0.f;
        for (int k = lane; k < HH; k += 32) acc = fmaf(kr[k], sh[k], acc);
#pragma unroll
        for (int o = 16; o; o >>= 1) acc += __shfl_xor_sync(0xffffffffu, acc, o);
        if (lane == 0) sa[s] = acc;
    }
    __syncthreads();

    int len = enc_len[b];
    float sc   = (tid < SS) ? sa[tid] : -INFINITY;
    bool valid = (tid < SS) && (tid < len);
    float v    = valid ? sc : -INFINITY;

    // block max
    float m = v;
#pragma unroll
    for (int o = 16; o; o >>= 1) m = fmaxf(m, __shfl_xor_sync(0xffffffffu, m, o));
    if (lane == 0) red[warp] = m;
    __syncthreads();
    if (tid == 0) {
        float mm = red[0];
        for (int i = 1; i < 8; i++) mm = fmaxf(mm, red[i]);
        bc = mm;
    }
    __syncthreads();
    float mx = bc;

    // block sum of exp
    float e = valid ? expf(sc - mx) : 0.f;
    float s2 = e;
#pragma unroll
    for (int o = 16; o; o >>= 1) s2 += __shfl_xor_sync(0xffffffffu, s2, o);
    __syncthreads();
    if (lane == 0) red[warp] = s2;
    __syncthreads();
    if (tid == 0) {
        float t2 = 0.f;
        for (int i = 0; i < 8; i++) t2 += red[i];
        bc = t2;
    }
    __syncthreads();
    float inv = 1.f / bc;
    if (tid < SS) sa[tid] = e * inv;
    __syncthreads();

    // c_t[e] = sum_s alpha[s] * enc[b,s,e]  (float4 per thread: 256*4 = 1024)
    float4 ct = make_float4(0.f, 0.f, 0.f, 0.f);
    for (int s = 0; s < len; s++) {
        float a = sa[s];
        float4 ev = ((const float4*)(enc + ((size_t)b * SS + s) * EE))[tid];
        ct.x = fmaf(a, ev.x, ct.x);
        ct.y = fmaf(a, ev.y, ct.y);
        ct.z = fmaf(a, ev.z, ct.z);
        ct.w = fmaf(a, ev.w, ct.w);
    }
    ((float4*)&g_hc[b * 2048 + HH])[tid] = ct;
}

// ---------------------------------------------------------------------------
// Greedy argmax over logits row + embedding gather -> xcat[:, :512]
// ---------------------------------------------------------------------------
__global__ void __launch_bounds__(512)
argmax_embed(const float* __restrict__ logits, const float* __restrict__ emb, int t)
{
    int b = blockIdx.x;
    const float* row = logits + ((size_t)b * TT + t) * VV;
    int tid = threadIdx.x;   // 512

    float bv = -INFINITY;
    int   bi = 0x7fffffff;
    for (int vi = tid; vi < VV; vi += 512) {
        float x = row[vi];
        if (x > bv || (x == bv && vi < bi)) { bv = x; bi = vi; }
    }
#pragma unroll
    for (int o = 16; o; o >>= 1) {
        float ov = __shfl_xor_sync(0xffffffffu, bv, o);
        int   oi = __shfl_xor_sync(0xffffffffu, bi, o);
        if (ov > bv || (ov == bv && oi < bi)) { bv = ov; bi = oi; }
    }
    __shared__ float sv[16];
    __shared__ int   si[16];
    __shared__ int   ssym;
    int warp = tid >> 5, lane = tid & 31;
    if (lane == 0) { sv[warp] = bv; si[warp] = bi; }
    __syncthreads();
    if (warp == 0) {
        bv = (lane < 16) ? sv[lane] : -INFINITY;
        bi = (lane < 16) ? si[lane] : 0x7fffffff;
#pragma unroll
        for (int o = 16; o; o >>= 1) {
            float ov = __shfl_xor_sync(0xffffffffu, bv, o);
            int   oi = __shfl_xor_sync(0xffffffffu, bi, o);
            if (ov > bv || (ov == bv && oi < bi)) { bv = ov; bi = oi; }
        }
        if (lane == 0) ssym = bi;
    }
    __syncthreads();
    int sym = ssym;
    g_xcat[b * KCAT + tid] = emb[(size_t)sym * EMBD + tid];  // tid < 512 = EMBD
}

// ---------------------------------------------------------------------------
// Fused in-place log-softmax over each [VV] row of d_out  (1 read + 1 write)
// ---------------------------------------------------------------------------
__global__ void __launch_bounds__(1024)
logsoftmax_rows(float* __restrict__ out)
{
    float* p = out + (size_t)blockIdx.x * VV;
    int tid = threadIdx.x;

    float x[32];
    float mx = -INFINITY;
#pragma unroll
    for (int i = 0; i < 32; i++) {
        int v = tid + (i << 10);
        x[i] = (v < VV) ? p[v] : -INFINITY;
        mx = fmaxf(mx, x[i]);
    }

    __shared__ float red[32];
    __shared__ float bc;
#pragma unroll
    for (int o = 16; o; o >>= 1) mx = fmaxf(mx, __shfl_xor_sync(0xffffffffu, mx, o));
    if ((tid & 31) == 0) red[tid >> 5] = mx;
    __syncthreads();
    if (tid < 32) {
        float m = red[tid];
#pragma unroll
        for (int o = 16; o; o >>= 1) m = fmaxf(m, __shfl_xor_sync(0xffffffffu, m, o));
        if (tid == 0) bc = m;
    }
    __syncthreads();
    float M = bc;

    float s = 0.f;
#pragma unroll
    for (int i = 0; i < 32; i++) s += expf(x[i] - M);   // expf(-inf)=0
    __syncthreads();                                    // guard red/bc reuse
#pragma unroll
    for (int o = 16; o; o >>= 1) s += __shfl_xor_sync(0xffffffffu, s, o);
    if ((tid & 31) == 0) red[tid >> 5] = s;
    __syncthreads();
    if (tid < 32) {
        float m = red[tid];
#pragma unroll
        for (int o = 16; o; o >>= 1) m += __shfl_xor_sync(0xffffffffu, m, o);
        if (tid == 0) bc = m;
    }
    __syncthreads();
    float lz = M + logf(bc);
#pragma unroll
    for (int i = 0; i < 32; i++) {
        int v = tid + (i << 10);
        if (v < VV) p[v] = x[i] - lz;
    }
}

__global__ void fill_tail(float* __restrict__ p, long n, float val)
{
    long i = (long)blockIdx.x * blockDim.x + threadIdx.x;
    if (i < n) p[i] = val;
}

// ---------------------------------------------------------------------------
// Launch
// ---------------------------------------------------------------------------
extern "C" void kernel_launch(void* const* d_in, const int* in_sizes, int n_in,
                              void* d_out, int out_size)
{
    const float* dec_init  = (const float*)d_in[0];
    const float* enc       = (const float*)d_in[1];
    const int*   enc_len   = (const int*)d_in[2];
    /* d_in[3] = tgt (unused in eval mode) */
    const float* W_ih      = (const float*)d_in[4];
    const float* W_hh      = (const float*)d_in[5];
    const float* b_lstm    = (const float*)d_in[6];
    const float* W_attproj = (const float*)d_in[7];
    const float* W_out     = (const float*)d_in[8];
    const float* W_vocab   = (const float*)d_in[9];
    const float* emb       = (const float*)d_in[10];
    float* out = (float*)d_out;

    void *p_keys, *p_wcat, *p_xcat, *p_hc, *p_gates, *p_dec;
    cudaGetSymbolAddress(&p_keys,  g_keys);
    cudaGetSymbolAddress(&p_wcat,  g_wcat);
    cudaGetSymbolAddress(&p_xcat,  g_xcat);
    cudaGetSymbolAddress(&p_hc,    g_hc);
    cudaGetSymbolAddress(&p_gates, g_gates);
    cudaGetSymbolAddress(&p_dec,   g_dec);

    // one-time-per-call setup
    build_wcat<<<2048, 256>>>(W_ih, W_hh);
    init_state<<<(BB * HH) / 256, 256>>>(dec_init);
    // keys[B*S, H] = enc[B*S, E] @ W_attproj^T
    sgemm_abt<64><<<dim3(HH / 64, (BB * SS) / 64), 256>>>(
        enc, EE, W_attproj, EE, (float*)p_keys, HH,
        BB * SS, HH, EE, nullptr);

    for (int t = 0; t < TT; t++) {
        // gates = xcat @ Wcat^T + b
        sgemm_abt<32><<<dim3(NGATE / 32, 1), 256>>>(
            (const float*)p_xcat, KCAT, (const float*)p_wcat, KCAT,
            (float*)p_gates, NGATE, BB, NGATE, KCAT, b_lstm);
        lstm_cell<<<(BB * HH) / 256, 256>>>();
        attention<<<BB, 256>>>(enc, enc_len);
        // dec = [h | c_t] @ W_out^T
        sgemm_abt<16><<<dim3(EMBD / 16, 1), 256>>>(
            (const float*)p_hc, 2048, W_out, 2048,
            (float*)p_dec, EMBD, BB, EMBD, 2048, nullptr);
        // logits -> directly into d_out[b, t, :]
        sgemm_abt<64><<<dim3(VV / 64, 1), 256>>>(
            (const float*)p_dec, EMBD, W_vocab, EMBD,
            out + (size_t)t * VV, (size_t)TT * VV, BB, VV, EMBD, nullptr);
        argmax_embed<<<BB, 512>>>(out, emb, t);
    }

    // final log-softmax in place over all B*T rows
    logsoftmax_rows<<<BB * TT, 1024>>>(out);

    // tgt_len output: always T (== 50) per the reference's final where()
    long extra = (long)out_size - (long)BB * TT * VV;
    if (extra > 0)
        fill_tail<<<(unsigned)((extra + 255) / 256), 256>>>(
            out + (size_t)BB * TT * VV, extra, 50.0f);
}

// round 5
// speedup vs baseline: 2.4501x; 2.4501x over previous
#include <cuda_runtime.h>
#include <math.h>

// Problem constants (fixed by the reference)
#define BB   64
#define SS   128
#define HH   1024
#define EE   1024
#define EMBD 512
#define VV   32000
#define TT   50
#define KCAT 1536          // EMBD + HH
#define NGATE 4096         // 4*HH
#define GSPLIT 4           // split-K for gates GEMM
#define OSPLIT 16          // split-K for out-projection GEMM

// ---------------------------------------------------------------------------
// Device scratch (static device globals — no allocation)
// ---------------------------------------------------------------------------
__device__ float g_keys[(size_t)BB * SS * HH];       // att keys [B,S,H]
__device__ float g_wcat[(size_t)NGATE * KCAT];       // [W_ih | W_hh]
__device__ float g_xcat[BB * KCAT];                  // [prev_emb | h]
__device__ float g_hc[BB * 2048];                    // [h | c_t]
__device__ float g_c[BB * HH];                       // LSTM cell state
__device__ float g_gpart[GSPLIT * BB * NGATE];       // gates partials
__device__ float g_dpart[OSPLIT * BB * EMBD];        // out-proj partials
__device__ float g_dec[BB * EMBD];                   // out-projection result
__device__ float g_scores[BB * SS];                  // attention scores

// ---------------------------------------------------------------------------
// Double-buffered SGEMM:  C[M,N] = A[M,K]*B[N,K]^T
// Block tile 64x64, TK=32, 256 threads, 4x4 micro-tile, float4 everywhere.
// blockIdx.x -> N tile, blockIdx.y -> M tile, blockIdx.z -> split-K slice.
// Requires: lda/ldb/kLen multiples of 4, kLen % 32 == 0, M,N multiples of 64.
// ---------------------------------------------------------------------------
__global__ void __launch_bounds__(256)
sgemm64(const float* __restrict__ A, int lda,
        const float* __restrict__ B, int ldb,
        float* __restrict__ C, size_t ldc, size_t splitStride, int kLen)
{
    constexpr int TM = 64, TN = 64, TK = 32;
    __shared__ float As[2][TK][TM + 4];
    __shared__ float Bs[2][TK][TN + 4];

    const int tid = threadIdx.x;
    const int m0  = blockIdx.y * TM;
    const int n0  = blockIdx.x * TN;

    A += (size_t)m0 * lda + (size_t)blockIdx.z * kLen;
    B += (size_t)n0 * ldb + (size_t)blockIdx.z * kLen;
    C += (size_t)blockIdx.z * splitStride + (size_t)m0 * ldc + n0;

    const int lr  = tid >> 2;        // loader row 0..63
    const int lc4 = tid & 3;         // loader float4 col 0..3 (+4 for 2nd)
    const int tx  = tid & 15;        // n-group
    const int ty  = tid >> 4;        // m-group

    const float* Ald = A + (size_t)lr * lda + lc4 * 4;
    const float* Bld = B + (size_t)lr * ldb + lc4 * 4;

    float4 ra0 = *(const float4*)(Ald);
    float4 ra1 = *(const float4*)(Ald + 16);
    float4 rb0 = *(const float4*)(Bld);
    float4 rb1 = *(const float4*)(Bld + 16);

    float acc[4][4];
#pragma unroll
    for (int i = 0; i < 4; i++)
#pragma unroll
        for (int j = 0; j < 4; j++) acc[i][j] = 0.f;

    const int nk = kLen / TK;
    int buf = 0;

#define STORE_TILE(bf)                                                        \
    {   int kk0 = lc4 * 4;                                                    \
        As[bf][kk0+ 0][lr]=ra0.x; As[bf][kk0+ 1][lr]=ra0.y;                   \
        As[bf][kk0+ 2][lr]=ra0.z; As[bf][kk0+ 3][lr]=ra0.w;                   \
        As[bf][kk0+16][lr]=ra1.x; As[bf][kk0+17][lr]=ra1.y;                   \
        As[bf][kk0+18][lr]=ra1.z; As[bf][kk0+19][lr]=ra1.w;                   \
        Bs[bf][kk0+ 0][lr]=rb0.x; Bs[bf][kk0+ 1][lr]=rb0.y;                   \
        Bs[bf][kk0+ 2][lr]=rb0.z; Bs[bf][kk0+ 3][lr]=rb0.w;                   \
        Bs[bf][kk0+16][lr]=rb1.x; Bs[bf][kk0+17][lr]=rb1.y;                   \
        Bs[bf][kk0+18][lr]=rb1.z; Bs[bf][kk0+19][lr]=rb1.w; }

    STORE_TILE(0);
    __syncthreads();

    for (int kt = 0; kt < nk; kt++) {
        if (kt + 1 < nk) {                      // prefetch next tile to regs
            const float* Ap = Ald + (kt + 1) * TK;
            const float* Bp = Bld + (kt + 1) * TK;
            ra0 = *(const float4*)(Ap);
            ra1 = *(const float4*)(Ap + 16);
            rb0 = *(const float4*)(Bp);
            rb1 = *(const float4*)(Bp + 16);
        }
#pragma unroll
        for (int k = 0; k < TK; k++) {
            float4 a = *(const float4*)&As[buf][k][ty * 4];
            float4 b = *(const float4*)&Bs[buf][k][tx * 4];
            acc[0][0]=fmaf(a.x,b.x,acc[0][0]); acc[0][1]=fmaf(a.x,b.y,acc[0][1]);
            acc[0][2]=fmaf(a.x,b.z,acc[0][2]); acc[0][3]=fmaf(a.x,b.w,acc[0][3]);
            acc[1][0]=fmaf(a.y,b.x,acc[1][0]); acc[1][1]=fmaf(a.y,b.y,acc[1][1]);
            acc[1][2]=fmaf(a.y,b.z,acc[1][2]); acc[1][3]=fmaf(a.y,b.w,acc[1][3]);
            acc[2][0]=fmaf(a.z,b.x,acc[2][0]); acc[2][1]=fmaf(a.z,b.y,acc[2][1]);
            acc[2][2]=fmaf(a.z,b.z,acc[2][2]); acc[2][3]=fmaf(a.z,b.w,acc[2][3]);
            acc[3][0]=fmaf(a.w,b.x,acc[3][0]); acc[3][1]=fmaf(a.w,b.y,acc[3][1]);
            acc[3][2]=fmaf(a.w,b.z,acc[3][2]); acc[3][3]=fmaf(a.w,b.w,acc[3][3]);
        }
        if (kt + 1 < nk) {
            __syncthreads();
            STORE_TILE(buf ^ 1);
            __syncthreads();
            buf ^= 1;
        }
    }
#undef STORE_TILE

#pragma unroll
    for (int i = 0; i < 4; i++) {
        float4 o = make_float4(acc[i][0], acc[i][1], acc[i][2], acc[i][3]);
        *(float4*)(C + (size_t)(ty * 4 + i) * ldc + tx * 4) = o;
    }
}

// ---------------------------------------------------------------------------
// Setup kernels
// ---------------------------------------------------------------------------
__global__ void build_wcat(const float* __restrict__ W_ih,
                           const float* __restrict__ W_hh)
{
    size_t total = (size_t)NGATE * KCAT;
    for (size_t i = (size_t)blockIdx.x * blockDim.x + threadIdx.x; i < total;
         i += (size_t)gridDim.x * blockDim.x) {
        int j = (int)(i / KCAT);
        int k = (int)(i % KCAT);
        g_wcat[i] = (k < EMBD) ? W_ih[(size_t)j * EMBD + k]
                               : W_hh[(size_t)j * HH + (k - EMBD)];
    }
}

__global__ void init_state(const float* __restrict__ dec_init)
{
    int idx = blockIdx.x * blockDim.x + threadIdx.x;   // B*H
    int b = idx >> 10, j = idx & 1023;
    float h0 = dec_init[idx];
    g_hc[b * 2048 + j] = h0;
    g_xcat[b * KCAT + EMBD + j] = h0;
    g_c[idx] = dec_init[BB * HH + idx];
    if (j < EMBD) g_xcat[b * KCAT + j] = 0.f;
}

// ---------------------------------------------------------------------------
// LSTM cell: sum GSPLIT gate partials + bias, apply nonlinearity
// ---------------------------------------------------------------------------
__device__ __forceinline__ float sigf(float x) { return 1.f / (1.f + expf(-x)); }

__global__ void lstm_cell(const float* __restrict__ b_lstm)
{
    int idx = blockIdx.x * blockDim.x + threadIdx.x;   // B*H
    int b = idx >> 10, j = idx & 1023;
    const float* gp = g_gpart + (size_t)b * NGATE;
    const size_t SP = (size_t)BB * NGATE;
    float ig = b_lstm[j], fg = b_lstm[1024 + j],
          gg = b_lstm[2048 + j], og = b_lstm[3072 + j];
#pragma unroll
    for (int s = 0; s < GSPLIT; s++) {
        ig += gp[s * SP + j];
        fg += gp[s * SP + 1024 + j];
        gg += gp[s * SP + 2048 + j];
        og += gp[s * SP + 3072 + j];
    }
    float c = sigf(fg) * g_c[idx] + sigf(ig) * tanhf(gg);
    float h = sigf(og) * tanhf(c);
    g_c[idx] = c;
    g_hc[b * 2048 + j] = h;
    g_xcat[b * KCAT + EMBD + j] = h;
}

// ---------------------------------------------------------------------------
// Attention scores: grid (4, B); each block does 32 rows of keys . h
// ---------------------------------------------------------------------------
__global__ void __launch_bounds__(256)
attn_scores()
{
    int b = blockIdx.y;
    int tid = threadIdx.x, warp = tid >> 5, lane = tid & 31;
    __shared__ float4 sh4[HH / 4];

    const float4* h4 = (const float4*)&g_hc[b * 2048];
    sh4[tid] = h4[tid];                       // 256 float4 = 1024 floats
    __syncthreads();

#pragma unroll
    for (int r = 0; r < 4; r++) {
        int s = blockIdx.x * 32 + warp * 4 + r;
        const float4* k4 = (const float4*)&g_keys[((size_t)b * SS + s) * HH];
        float acc = 0.f;
#pragma unroll
        for (int i = 0; i < 8; i++) {
            float4 kv = k4[lane + 32 * i];
            float4 hv = sh4[lane + 32 * i];
            acc = fmaf(kv.x, hv.x, acc);
            acc = fmaf(kv.y, hv.y, acc);
            acc = fmaf(kv.z, hv.z, acc);
            acc = fmaf(kv.w, hv.w, acc);
        }
#pragma unroll
        for (int o = 16; o; o >>= 1) acc += __shfl_xor_sync(0xffffffffu, acc, o);
        if (lane == 0) g_scores[b * SS + s] = acc;
    }
}

// ---------------------------------------------------------------------------
// Attention context (softmax fused, recomputed per block): grid (4, B)
// Each block computes 256 dims of c_t for batch b.
// ---------------------------------------------------------------------------
__global__ void __launch_bounds__(256)
attn_context(const float* __restrict__ enc, const int* __restrict__ enc_len)
{
    int b = blockIdx.y, e0 = blockIdx.x * 256;
    int tid = threadIdx.x, warp = tid >> 5, lane = tid & 31;
    __shared__ float sa[SS];
    __shared__ float red[8];
    __shared__ float bc;

    int len = enc_len[b];
    float v = -1e9f;
    if (tid < SS) {
        float s = g_scores[b * SS + tid];
        v = (tid < len) ? s : -1e9f;
        sa[tid] = v;
    }
    // block max over 128 entries (warps 0-3 hold them)
    float m = v;
#pragma unroll
    for (int o = 16; o; o >>= 1) m = fmaxf(m, __shfl_xor_sync(0xffffffffu, m, o));
    if (lane == 0) red[warp] = m;
    __syncthreads();
    if (tid == 0) {
        float mm = red[0];
        for (int i = 1; i < 4; i++) mm = fmaxf(mm, red[i]);
        bc = mm;
    }
    __syncthreads();
    float mx = bc;

    float e = (tid < SS) ? expf(v - mx) : 0.f;   // exp(-1e9-mx)==0 exactly
    float s2 = e;
#pragma unroll
    for (int o = 16; o; o >>= 1) s2 += __shfl_xor_sync(0xffffffffu, s2, o);
    __syncthreads();
    if (lane == 0) red[warp] = s2;
    __syncthreads();
    if (tid == 0) bc = red[0] + red[1] + red[2] + red[3];
    __syncthreads();
    float inv = 1.f / bc;
    if (tid < SS) sa[tid] = e * inv;
    __syncthreads();

    const float* ep = enc + ((size_t)b * SS) * EE + e0 + tid;
    float acc = 0.f;
    int s = 0;
    for (; s + 4 <= len; s += 4) {
        float x0 = ep[(size_t)(s + 0) * EE];
        float x1 = ep[(size_t)(s + 1) * EE];
        float x2 = ep[(size_t)(s + 2) * EE];
        float x3 = ep[(size_t)(s + 3) * EE];
        acc = fmaf(sa[s + 0], x0, acc);
        acc = fmaf(sa[s + 1], x1, acc);
        acc = fmaf(sa[s + 2], x2, acc);
        acc = fmaf(sa[s + 3], x3, acc);
    }
    for (; s < len; s++) acc = fmaf(sa[s], ep[(size_t)s * EE], acc);
    g_hc[b * 2048 + HH + e0 + tid] = acc;
}

// ---------------------------------------------------------------------------
// Reduce out-projection split-K partials
// ---------------------------------------------------------------------------
__global__ void reduce_dec()
{
    int idx = blockIdx.x * blockDim.x + threadIdx.x;   // B*EMBD = 32768
    float a = 0.f;
#pragma unroll
    for (int s = 0; s < OSPLIT; s++) a += g_dpart[(size_t)s * BB * EMBD + idx];
    g_dec[idx] = a;
}

// ---------------------------------------------------------------------------
// Greedy argmax over logits row + embedding gather
// ---------------------------------------------------------------------------
__global__ void __launch_bounds__(1024)
argmax_embed(const float* __restrict__ logits, const float* __restrict__ emb, int t)
{
    int b = blockIdx.x;
    const float4* row4 = (const float4*)(logits + ((size_t)b * TT + t) * VV);
    int tid = threadIdx.x;

    float bv = -INFINITY;
    int   bi = 0x7fffffff;
#pragma unroll
    for (int j = 0; j < 8; j++) {
        int v4 = j * 1024 + tid;
        if (v4 < VV / 4) {
            float4 x = row4[v4];
            int base = v4 * 4;
            if (x.x > bv || (x.x == bv && base     < bi)) { bv = x.x; bi = base;     }
            if (x.y > bv || (x.y == bv && base + 1 < bi)) { bv = x.y; bi = base + 1; }
            if (x.z > bv || (x.z == bv && base + 2 < bi)) { bv = x.z; bi = base + 2; }
            if (x.w > bv || (x.w == bv && base + 3 < bi)) { bv = x.w; bi = base + 3; }
        }
    }
#pragma unroll
    for (int o = 16; o; o >>= 1) {
        float ov = __shfl_xor_sync(0xffffffffu, bv, o);
        int   oi = __shfl_xor_sync(0xffffffffu, bi, o);
        if (ov > bv || (ov == bv && oi < bi)) { bv = ov; bi = oi; }
    }
    __shared__ float sv[32];
    __shared__ int   si[32];
    __shared__ int   ssym;
    int warp = tid >> 5, lane = tid & 31;
    if (lane == 0) { sv[warp] = bv; si[warp] = bi; }
    __syncthreads();
    if (warp == 0) {
        bv = sv[lane]; bi = si[lane];
#pragma unroll
        for (int o = 16; o; o >>= 1) {
            float ov = __shfl_xor_sync(0xffffffffu, bv, o);
            int   oi = __shfl_xor_sync(0xffffffffu, bi, o);
            if (ov > bv || (ov == bv && oi < bi)) { bv = ov; bi = oi; }
        }
        if (lane == 0) ssym = bi;
    }
    __syncthreads();
    int sym = ssym;
    if (tid < EMBD / 4) {
        const float4* er = (const float4*)(emb + (size_t)sym * EMBD);
        ((float4*)&g_xcat[b * KCAT])[tid] = er[tid];
    }
}

// ---------------------------------------------------------------------------
// Fused in-place log-softmax over each [VV] row of d_out
// ---------------------------------------------------------------------------
__global__ void __launch_bounds__(1024)
logsoftmax_rows(float* __restrict__ out)
{
    float* p = out + (size_t)blockIdx.x * VV;
    int tid = threadIdx.x;

    float x[32];
    float mx = -INFINITY;
#pragma unroll
    for (int i = 0; i < 32; i++) {
        int v = tid + (i << 10);
        x[i] = (v < VV) ? p[v] : -INFINITY;
        mx = fmaxf(mx, x[i]);
    }
    __shared__ float red[32];
    __shared__ float bc;
#pragma unroll
    for (int o = 16; o; o >>= 1) mx = fmaxf(mx, __shfl_xor_sync(0xffffffffu, mx, o));
    if ((tid & 31) == 0) red[tid >> 5] = mx;
    __syncthreads();
    if (tid < 32) {
        float m = red[tid];
#pragma unroll
        for (int o = 16; o; o >>= 1) m = fmaxf(m, __shfl_xor_sync(0xffffffffu, m, o));
        if (tid == 0) bc = m;
    }
    __syncthreads();
    float M = bc;

    float s = 0.f;
#pragma unroll
    for (int i = 0; i < 32; i++) s += expf(x[i] - M);
    __syncthreads();
#pragma unroll
    for (int o = 16; o; o >>= 1) s += __shfl_xor_sync(0xffffffffu, s, o);
    if ((tid & 31) == 0) red[tid >> 5] = s;
    __syncthreads();
    if (tid < 32) {
        float m = red[tid];
#pragma unroll
        for (int o = 16; o; o >>= 1) m += __shfl_xor_sync(0xffffffffu, m, o);
        if (tid == 0) bc = m;
    }
    __syncthreads();
    float lz = M + logf(bc);
#pragma unroll
    for (int i = 0; i < 32; i++) {
        int v = tid + (i << 10);
        if (v < VV) p[v] = x[i] - lz;
    }
}

__global__ void fill_tail(float* __restrict__ p, long n, float val)
{
    long i = (long)blockIdx.x * blockDim.x + threadIdx.x;
    if (i < n) p[i] = val;
}

// ---------------------------------------------------------------------------
// Launch
// ---------------------------------------------------------------------------
extern "C" void kernel_launch(void* const* d_in, const int* in_sizes, int n_in,
                              void* d_out, int out_size)
{
    const float* dec_init  = (const float*)d_in[0];
    const float* enc       = (const float*)d_in[1];
    const int*   enc_len   = (const int*)d_in[2];
    /* d_in[3] = tgt (unused in eval mode) */
    const float* W_ih      = (const float*)d_in[4];
    const float* W_hh      = (const float*)d_in[5];
    const float* b_lstm    = (const float*)d_in[6];
    const float* W_attproj = (const float*)d_in[7];
    const float* W_out     = (const float*)d_in[8];
    const float* W_vocab   = (const float*)d_in[9];
    const float* emb       = (const float*)d_in[10];
    float* out = (float*)d_out;

    void *p_keys, *p_wcat, *p_xcat, *p_hc, *p_gpart, *p_dpart, *p_dec;
    cudaGetSymbolAddress(&p_keys,  g_keys);
    cudaGetSymbolAddress(&p_wcat,  g_wcat);
    cudaGetSymbolAddress(&p_xcat,  g_xcat);
    cudaGetSymbolAddress(&p_hc,    g_hc);
    cudaGetSymbolAddress(&p_gpart, g_gpart);
    cudaGetSymbolAddress(&p_dpart, g_dpart);
    cudaGetSymbolAddress(&p_dec,   g_dec);

    // one-time setup
    build_wcat<<<2048, 256>>>(W_ih, W_hh);
    init_state<<<(BB * HH) / 256, 256>>>(dec_init);
    // keys[B*S, H] = enc[B*S, E] @ W_attproj^T   (2048 blocks)
    sgemm64<<<dim3(HH / 64, (BB * SS) / 64, 1), 256>>>(
        enc, EE, W_attproj, EE, (float*)p_keys, HH, 0, EE);

    for (int t = 0; t < TT; t++) {
        // gates partials: split-K x4  (256 blocks)
        sgemm64<<<dim3(NGATE / 64, 1, GSPLIT), 256>>>(
            (const float*)p_xcat, KCAT, (const float*)p_wcat, KCAT,
            (float*)p_gpart, NGATE, (size_t)BB * NGATE, KCAT / GSPLIT);
        lstm_cell<<<(BB * HH) / 256, 256>>>(b_lstm);
        attn_scores<<<dim3(4, BB), 256>>>();
        attn_context<<<dim3(4, BB), 256>>>(enc, enc_len);
        // dec partials: split-K x16  (128 blocks)
        sgemm64<<<dim3(EMBD / 64, 1, OSPLIT), 256>>>(
            (const float*)p_hc, 2048, W_out, 2048,
            (float*)p_dpart, EMBD, (size_t)BB * EMBD, 2048 / OSPLIT);
        reduce_dec<<<(BB * EMBD) / 256, 256>>>();
        // vocab logits straight into d_out[b, t, :]  (500 blocks)
        sgemm64<<<dim3(VV / 64, 1, 1), 256>>>(
            (const float*)p_dec, EMBD, W_vocab, EMBD,
            out + (size_t)t * VV, (size_t)TT * VV, 0, EMBD);
        argmax_embed<<<BB, 1024>>>(out, emb, t);
    }

    // final log-softmax in place over all B*T rows
    logsoftmax_rows<<<BB * TT, 1024>>>(out);

    // tgt_len output: always T (== 50) per the reference's final where()
    long extra = (long)out_size - (long)BB * TT * VV;
    if (extra > 0)
        fill_tail<<<(unsigned)((extra + 255) / 256), 256>>>(
            out + (size_t)BB * TT * VV, extra, 50.0f);
}

// round 6
// speedup vs baseline: 2.4680x; 1.0073x over previous
#include <cuda_runtime.h>
#include <math.h>

// Problem constants (fixed by the reference)
#define BB   64
#define SS   128
#define HH   1024
#define EE   1024
#define EMBD 512
#define VV   32000
#define TT   50
#define KCAT 1536          // EMBD + HH
#define NGATE 4096         // 4*HH
#define GSPLIT 4           // split-K for gates GEMM
#define OSPLIT 16          // split-K for out-projection GEMM

// ---------------------------------------------------------------------------
// Device scratch (static device globals — no allocation)
// ---------------------------------------------------------------------------
__device__ float g_keys[(size_t)BB * SS * HH];       // att keys [B,S,H]
__device__ float g_wcat[(size_t)NGATE * KCAT];       // [W_ih | W_hh]
__device__ float g_xcat[BB * KCAT];                  // [prev_emb | h]
__device__ float g_hc[BB * 2048];                    // [h | c_t]
__device__ float g_c[BB * HH];                       // LSTM cell state
__device__ float g_gpart[GSPLIT * BB * NGATE];       // gates partials
__device__ float g_dpart[OSPLIT * BB * EMBD];        // out-proj partials
__device__ float g_dec[BB * EMBD];                   // out-projection result
__device__ float g_scores[BB * SS];                  // attention scores

// ---------------------------------------------------------------------------
// Double-buffered SGEMM:  C[M,N] = A[M,K]*B[N,K]^T
// Block tile 64x64, TK=32, 256 threads, 4x4 micro-tile, float4 everywhere.
// blockIdx.x -> N tile, blockIdx.y -> M tile, blockIdx.z -> split-K slice.
// Requires: lda/ldb/kLen multiples of 4, kLen % 32 == 0, M,N multiples of 64.
// ---------------------------------------------------------------------------
__global__ void __launch_bounds__(256)
sgemm64(const float* __restrict__ A, int lda,
        const float* __restrict__ B, int ldb,
        float* __restrict__ C, size_t ldc, size_t splitStride, int kLen)
{
    constexpr int TM = 64, TN = 64, TK = 32;
    __shared__ float As[2][TK][TM + 4];
    __shared__ float Bs[2][TK][TN + 4];

    const int tid = threadIdx.x;
    const int m0  = blockIdx.y * TM;
    const int n0  = blockIdx.x * TN;

    A += (size_t)m0 * lda + (size_t)blockIdx.z * kLen;
    B += (size_t)n0 * ldb + (size_t)blockIdx.z * kLen;
    C += (size_t)blockIdx.z * splitStride + (size_t)m0 * ldc + n0;

    const int lr  = tid >> 2;        // loader row 0..63
    const int lc4 = tid & 3;         // loader float4 col 0..3 (+4 for 2nd)
    const int tx  = tid & 15;        // n-group
    const int ty  = tid >> 4;        // m-group

    const float* Ald = A + (size_t)lr * lda + lc4 * 4;
    const float* Bld = B + (size_t)lr * ldb + lc4 * 4;

    float4 ra0 = *(const float4*)(Ald);
    float4 ra1 = *(const float4*)(Ald + 16);
    float4 rb0 = *(const float4*)(Bld);
    float4 rb1 = *(const float4*)(Bld + 16);

    float acc[4][4];
#pragma unroll
    for (int i = 0; i < 4; i++)
#pragma unroll
        for (int j = 0; j < 4; j++) acc[i][j] = 0.f;

    const int nk = kLen / TK;
    int buf = 0;

#define STORE_TILE(bf)                                                        \
    {   int kk0 = lc4 * 4;                                                    \
        As[bf][kk0+ 0][lr]=ra0.x; As[bf][kk0+ 1][lr]=ra0.y;                   \
        As[bf][kk0+ 2][lr]=ra0.z; As[bf][kk0+ 3][lr]=ra0.w;                   \
        As[bf][kk0+16][lr]=ra1.x; As[bf][kk0+17][lr]=ra1.y;                   \
        As[bf][kk0+18][lr]=ra1.z; As[bf][kk0+19][lr]=ra1.w;                   \
        Bs[bf][kk0+ 0][lr]=rb0.x; Bs[bf][kk0+ 1][lr]=rb0.y;                   \
        Bs[bf][kk0+ 2][lr]=rb0.z; Bs[bf][kk0+ 3][lr]=rb0.w;                   \
        Bs[bf][kk0+16][lr]=rb1.x; Bs[bf][kk0+17][lr]=rb1.y;                   \
        Bs[bf][kk0+18][lr]=rb1.z; Bs[bf][kk0+19][lr]=rb1.w; }

    STORE_TILE(0);
    __syncthreads();

    for (int kt = 0; kt < nk; kt++) {
        if (kt + 1 < nk) {                      // prefetch next tile to regs
            const float* Ap = Ald + (kt + 1) * TK;
            const float* Bp = Bld + (kt + 1) * TK;
            ra0 = *(const float4*)(Ap);
            ra1 = *(const float4*)(Ap + 16);
            rb0 = *(const float4*)(Bp);
            rb1 = *(const float4*)(Bp + 16);
        }
#pragma unroll
        for (int k = 0; k < TK; k++) {
            float4 a = *(const float4*)&As[buf][k][ty * 4];
            float4 b = *(const float4*)&Bs[buf][k][tx * 4];
            acc[0][0]=fmaf(a.x,b.x,acc[0][0]); acc[0][1]=fmaf(a.x,b.y,acc[0][1]);
            acc[0][2]=fmaf(a.x,b.z,acc[0][2]); acc[0][3]=fmaf(a.x,b.w,acc[0][3]);
            acc[1][0]=fmaf(a.y,b.x,acc[1][0]); acc[1][1]=fmaf(a.y,b.y,acc[1][1]);
            acc[1][2]=fmaf(a.y,b.z,acc[1][2]); acc[1][3]=fmaf(a.y,b.w,acc[1][3]);
            acc[2][0]=fmaf(a.z,b.x,acc[2][0]); acc[2][1]=fmaf(a.z,b.y,acc[2][1]);
            acc[2][2]=fmaf(a.z,b.z,acc[2][2]); acc[2][3]=fmaf(a.z,b.w,acc[2][3]);
            acc[3][0]=fmaf(a.w,b.x,acc[3][0]); acc[3][1]=fmaf(a.w,b.y,acc[3][1]);
            acc[3][2]=fmaf(a.w,b.z,acc[3][2]); acc[3][3]=fmaf(a.w,b.w,acc[3][3]);
        }
        if (kt + 1 < nk) {
            __syncthreads();
            STORE_TILE(buf ^ 1);
            __syncthreads();
            buf ^= 1;
        }
    }
#undef STORE_TILE

#pragma unroll
    for (int i = 0; i < 4; i++) {
        float4 o = make_float4(acc[i][0], acc[i][1], acc[i][2], acc[i][3]);
        *(float4*)(C + (size_t)(ty * 4 + i) * ldc + tx * 4) = o;
    }
}

// ---------------------------------------------------------------------------
// Setup kernels
// ---------------------------------------------------------------------------
__global__ void build_wcat(const float* __restrict__ W_ih,
                           const float* __restrict__ W_hh)
{
    size_t total = (size_t)NGATE * KCAT;
    for (size_t i = (size_t)blockIdx.x * blockDim.x + threadIdx.x; i < total;
         i += (size_t)gridDim.x * blockDim.x) {
        int j = (int)(i / KCAT);
        int k = (int)(i % KCAT);
        g_wcat[i] = (k < EMBD) ? W_ih[(size_t)j * EMBD + k]
                               : W_hh[(size_t)j * HH + (k - EMBD)];
    }
}

__global__ void init_state(const float* __restrict__ dec_init)
{
    int idx = blockIdx.x * blockDim.x + threadIdx.x;   // B*H
    int b = idx >> 10, j = idx & 1023;
    float h0 = dec_init[idx];
    g_hc[b * 2048 + j] = h0;
    g_xcat[b * KCAT + EMBD + j] = h0;
    g_c[idx] = dec_init[BB * HH + idx];
    if (j < EMBD) g_xcat[b * KCAT + j] = 0.f;
}

// ---------------------------------------------------------------------------
// LSTM cell: sum GSPLIT gate partials + bias, apply nonlinearity
// ---------------------------------------------------------------------------
__device__ __forceinline__ float sigf(float x) { return 1.f / (1.f + expf(-x)); }

__global__ void lstm_cell(const float* __restrict__ b_lstm)
{
    int idx = blockIdx.x * blockDim.x + threadIdx.x;   // B*H
    int b = idx >> 10, j = idx & 1023;
    const float* gp = g_gpart + (size_t)b * NGATE;
    const size_t SP = (size_t)BB * NGATE;
    float ig = b_lstm[j], fg = b_lstm[1024 + j],
          gg = b_lstm[2048 + j], og = b_lstm[3072 + j];
#pragma unroll
    for (int s = 0; s < GSPLIT; s++) {
        ig += gp[s * SP + j];
        fg += gp[s * SP + 1024 + j];
        gg += gp[s * SP + 2048 + j];
        og += gp[s * SP + 3072 + j];
    }
    float c = sigf(fg) * g_c[idx] + sigf(ig) * tanhf(gg);
    float h = sigf(og) * tanhf(c);
    g_c[idx] = c;
    g_hc[b * 2048 + j] = h;
    g_xcat[b * KCAT + EMBD + j] = h;
}

// ---------------------------------------------------------------------------
// Attention scores: grid (4, B); each block does 32 rows of keys . h
// ---------------------------------------------------------------------------
__global__ void __launch_bounds__(256)
attn_scores()
{
    int b = blockIdx.y;
    int tid = threadIdx.x, warp = tid >> 5, lane = tid & 31;
    __shared__ float4 sh4[HH / 4];

    const float4* h4 = (const float4*)&g_hc[b * 2048];
    sh4[tid] = h4[tid];                       // 256 float4 = 1024 floats
    __syncthreads();

#pragma unroll
    for (int r = 0; r < 4; r++) {
        int s = blockIdx.x * 32 + warp * 4 + r;
        const float4* k4 = (const float4*)&g_keys[((size_t)b * SS + s) * HH];
        float acc = 0.f;
#pragma unroll
        for (int i = 0; i < 8; i++) {
            float4 kv = k4[lane + 32 * i];
            float4 hv = sh4[lane + 32 * i];
            acc = fmaf(kv.x, hv.x, acc);
            acc = fmaf(kv.y, hv.y, acc);
            acc = fmaf(kv.z, hv.z, acc);
            acc = fmaf(kv.w, hv.w, acc);
        }
#pragma unroll
        for (int o = 16; o; o >>= 1) acc += __shfl_xor_sync(0xffffffffu, acc, o);
        if (lane == 0) g_scores[b * SS + s] = acc;
    }
}

// ---------------------------------------------------------------------------
// Attention context (softmax fused, recomputed per block): grid (4, B)
// Each block computes 256 dims of c_t for batch b.
// ---------------------------------------------------------------------------
__global__ void __launch_bounds__(256)
attn_context(const float* __restrict__ enc, const int* __restrict__ enc_len)
{
    int b = blockIdx.y, e0 = blockIdx.x * 256;
    int tid = threadIdx.x, warp = tid >> 5, lane = tid & 31;
    __shared__ float sa[SS];
    __shared__ float red[8];
    __shared__ float bc;

    int len = enc_len[b];
    float v = -1e9f;
    if (tid < SS) {
        float s = g_scores[b * SS + tid];
        v = (tid < len) ? s : -1e9f;
        sa[tid] = v;
    }
    // block max over 128 entries (warps 0-3 hold them)
    float m = v;
#pragma unroll
    for (int o = 16; o; o >>= 1) m = fmaxf(m, __shfl_xor_sync(0xffffffffu, m, o));
    if (lane == 0) red[warp] = m;
    __syncthreads();
    if (tid == 0) {
        float mm = red[0];
        for (int i = 1; i < 4; i++) mm = fmaxf(mm, red[i]);
        bc = mm;
    }
    __syncthreads();
    float mx = bc;

    float e = (tid < SS) ? expf(v - mx) : 0.f;   // exp(-1e9-mx)==0 exactly
    float s2 = e;
#pragma unroll
    for (int o = 16; o; o >>= 1) s2 += __shfl_xor_sync(0xffffffffu, s2, o);
    __syncthreads();
    if (lane == 0) red[warp] = s2;
    __syncthreads();
    if (tid == 0) bc = red[0] + red[1] + red[2] + red[3];
    __syncthreads();
    float inv = 1.f / bc;
    if (tid < SS) sa[tid] = e * inv;
    __syncthreads();

    const float* ep = enc + ((size_t)b * SS) * EE + e0 + tid;
    float acc = 0.f;
    int s = 0;
    for (; s + 4 <= len; s += 4) {
        float x0 = ep[(size_t)(s + 0) * EE];
        float x1 = ep[(size_t)(s + 1) * EE];
        float x2 = ep[(size_t)(s + 2) * EE];
        float x3 = ep[(size_t)(s + 3) * EE];
        acc = fmaf(sa[s + 0], x0, acc);
        acc = fmaf(sa[s + 1], x1, acc);
        acc = fmaf(sa[s + 2], x2, acc);
        acc = fmaf(sa[s + 3], x3, acc);
    }
    for (; s < len; s++) acc = fmaf(sa[s], ep[(size_t)s * EE], acc);
    g_hc[b * 2048 + HH + e0 + tid] = acc;
}

// ---------------------------------------------------------------------------
// Reduce out-projection split-K partials
// ---------------------------------------------------------------------------
__global__ void reduce_dec()
{
    int idx = blockIdx.x * blockDim.x + threadIdx.x;   // B*EMBD = 32768
    float a = 0.f;
#pragma unroll
    for (int s = 0; s < OSPLIT; s++) a += g_dpart[(size_t)s * BB * EMBD + idx];
    g_dec[idx] = a;
}

// ---------------------------------------------------------------------------
// Greedy argmax over logits row + embedding gather
// ---------------------------------------------------------------------------
__global__ void __launch_bounds__(1024)
argmax_embed(const float* __restrict__ logits, const float* __restrict__ emb, int t)
{
    int b = blockIdx.x;
    const float4* row4 = (const float4*)(logits + ((size_t)b * TT + t) * VV);
    int tid = threadIdx.x;

    float bv = -INFINITY;
    int   bi = 0x7fffffff;
#pragma unroll
    for (int j = 0; j < 8; j++) {
        int v4 = j * 1024 + tid;
        if (v4 < VV / 4) {
            float4 x = row4[v4];
            int base = v4 * 4;
            if (x.x > bv || (x.x == bv && base     < bi)) { bv = x.x; bi = base;     }
            if (x.y > bv || (x.y == bv && base + 1 < bi)) { bv = x.y; bi = base + 1; }
            if (x.z > bv || (x.z == bv && base + 2 < bi)) { bv = x.z; bi = base + 2; }
            if (x.w > bv || (x.w == bv && base + 3 < bi)) { bv = x.w; bi = base + 3; }
        }
    }
#pragma unroll
    for (int o = 16; o; o >>= 1) {
        float ov = __shfl_xor_sync(0xffffffffu, bv, o);
        int   oi = __shfl_xor_sync(0xffffffffu, bi, o);
        if (ov > bv || (ov == bv && oi < bi)) { bv = ov; bi = oi; }
    }
    __shared__ float sv[32];
    __shared__ int   si[32];
    __shared__ int   ssym;
    int warp = tid >> 5, lane = tid & 31;
    if (lane == 0) { sv[warp] = bv; si[warp] = bi; }
    __syncthreads();
    if (warp == 0) {
        bv = sv[lane]; bi = si[lane];
#pragma unroll
        for (int o = 16; o; o >>= 1) {
            float ov = __shfl_xor_sync(0xffffffffu, bv, o);
            int   oi = __shfl_xor_sync(0xffffffffu, bi, o);
            if (ov > bv || (ov == bv && oi < bi)) { bv = ov; bi = oi; }
        }
        if (lane == 0) ssym = bi;
    }
    __syncthreads();
    int sym = ssym;
    if (tid < EMBD / 4) {
        const float4* er = (const float4*)(emb + (size_t)sym * EMBD);
        ((float4*)&g_xcat[b * KCAT])[tid] = er[tid];
    }
}

// ---------------------------------------------------------------------------
// Fused in-place log-softmax over each [VV] row of d_out
// ---------------------------------------------------------------------------
__global__ void __launch_bounds__(1024)
logsoftmax_rows(float* __restrict__ out)
{
    float* p = out + (size_t)blockIdx.x * VV;
    int tid = threadIdx.x;

    float x[32];
    float mx = -INFINITY;
#pragma unroll
    for (int i = 0; i < 32; i++) {
        int v = tid + (i << 10);
        x[i] = (v < VV) ? p[v] : -INFINITY;
        mx = fmaxf(mx, x[i]);
    }
    __shared__ float red[32];
    __shared__ float bc;
#pragma unroll
    for (int o = 16; o; o >>= 1) mx = fmaxf(mx, __shfl_xor_sync(0xffffffffu, mx, o));
    if ((tid & 31) == 0) red[tid >> 5] = mx;
    __syncthreads();
    if (tid < 32) {
        float m = red[tid];
#pragma unroll
        for (int o = 16; o; o >>= 1) m = fmaxf(m, __shfl_xor_sync(0xffffffffu, m, o));
        if (tid == 0) bc = m;
    }
    __syncthreads();
    float M = bc;

    float s = 0.f;
#pragma unroll
    for (int i = 0; i < 32; i++) s += expf(x[i] - M);
    __syncthreads();
#pragma unroll
    for (int o = 16; o; o >>= 1) s += __shfl_xor_sync(0xffffffffu, s, o);
    if ((tid & 31) == 0) red[tid >> 5] = s;
    __syncthreads();
    if (tid < 32) {
        float m = red[tid];
#pragma unroll
        for (int o = 16; o; o >>= 1) m += __shfl_xor_sync(0xffffffffu, m, o);
        if (tid == 0) bc = m;
    }
    __syncthreads();
    float lz = M + logf(bc);
#pragma unroll
    for (int i = 0; i < 32; i++) {
        int v = tid + (i << 10);
        if (v < VV) p[v] = x[i] - lz;
    }
}

__global__ void fill_tail(float* __restrict__ p, long n, float val)
{
    long i = (long)blockIdx.x * blockDim.x + threadIdx.x;
    if (i < n) p[i] = val;
}

// ---------------------------------------------------------------------------
// Launch
// ---------------------------------------------------------------------------
extern "C" void kernel_launch(void* const* d_in, const int* in_sizes, int n_in,
                              void* d_out, int out_size)
{
    const float* dec_init  = (const float*)d_in[0];
    const float* enc       = (const float*)d_in[1];
    const int*   enc_len   = (const int*)d_in[2];
    /* d_in[3] = tgt (unused in eval mode) */
    const float* W_ih      = (const float*)d_in[4];
    const float* W_hh      = (const float*)d_in[5];
    const float* b_lstm    = (const float*)d_in[6];
    const float* W_attproj = (const float*)d_in[7];
    const float* W_out     = (const float*)d_in[8];
    const float* W_vocab   = (const float*)d_in[9];
    const float* emb       = (const float*)d_in[10];
    float* out = (float*)d_out;

    void *p_keys, *p_wcat, *p_xcat, *p_hc, *p_gpart, *p_dpart, *p_dec;
    cudaGetSymbolAddress(&p_keys,  g_keys);
    cudaGetSymbolAddress(&p_wcat,  g_wcat);
    cudaGetSymbolAddress(&p_xcat,  g_xcat);
    cudaGetSymbolAddress(&p_hc,    g_hc);
    cudaGetSymbolAddress(&p_gpart, g_gpart);
    cudaGetSymbolAddress(&p_dpart, g_dpart);
    cudaGetSymbolAddress(&p_dec,   g_dec);

    // one-time setup
    build_wcat<<<2048, 256>>>(W_ih, W_hh);
    init_state<<<(BB * HH) / 256, 256>>>(dec_init);
    // keys[B*S, H] = enc[B*S, E] @ W_attproj^T   (2048 blocks)
    sgemm64<<<dim3(HH / 64, (BB * SS) / 64, 1), 256>>>(
        enc, EE, W_attproj, EE, (float*)p_keys, HH, 0, EE);

    for (int t = 0; t < TT; t++) {
        // gates partials: split-K x4  (256 blocks)
        sgemm64<<<dim3(NGATE / 64, 1, GSPLIT), 256>>>(
            (const float*)p_xcat, KCAT, (const float*)p_wcat, KCAT,
            (float*)p_gpart, NGATE, (size_t)BB * NGATE, KCAT / GSPLIT);
        lstm_cell<<<(BB * HH) / 256, 256>>>(b_lstm);
        attn_scores<<<dim3(4, BB), 256>>>();
        attn_context<<<dim3(4, BB), 256>>>(enc, enc_len);
        // dec partials: split-K x16  (128 blocks)
        sgemm64<<<dim3(EMBD / 64, 1, OSPLIT), 256>>>(
            (const float*)p_hc, 2048, W_out, 2048,
            (float*)p_dpart, EMBD, (size_t)BB * EMBD, 2048 / OSPLIT);
        reduce_dec<<<(BB * EMBD) / 256, 256>>>();
        // vocab logits straight into d_out[b, t, :]  (500 blocks)
        sgemm64<<<dim3(VV / 64, 1, 1), 256>>>(
            (const float*)p_dec, EMBD, W_vocab, EMBD,
            out + (size_t)t * VV, (size_t)TT * VV, 0, EMBD);
        argmax_embed<<<BB, 1024>>>(out, emb, t);
    }

    // final log-softmax in place over all B*T rows
    logsoftmax_rows<<<BB * TT, 1024>>>(out);

    // tgt_len output: always T (== 50) per the reference's final where()
    long extra = (long)out_size - (long)BB * TT * VV;
    if (extra > 0)
        fill_tail<<<(unsigned)((extra + 255) / 256), 256>>>(
            out + (size_t)BB * TT * VV, extra, 50.0f);
}

// round 7
// speedup vs baseline: 2.4700x; 1.0008x over previous
#include <cuda_runtime.h>
#include <math.h>

// Problem constants (fixed by the reference)
#define BB   64
#define SS   128
#define HH   1024
#define EE   1024
#define EMBD 512
#define VV   32000
#define TT   50
#define KCAT 1536          // EMBD + HH
#define NGATE 4096         // 4*HH
#define GSPLIT 4           // split-K for gates GEMM
#define OSPLIT 16          // split-K for out-projection GEMM

// ---------------------------------------------------------------------------
// Device scratch (static device globals — no allocation)
// ---------------------------------------------------------------------------
__device__ float g_keys[(size_t)BB * SS * HH];       // att keys [B,S,H]
__device__ float g_wcat[(size_t)NGATE * KCAT];       // [W_ih | W_hh]
__device__ float g_xcat[BB * KCAT];                  // [prev_emb | h]
__device__ float g_hc[BB * 2048];                    // [h | c_t]
__device__ float g_c[BB * HH];                       // LSTM cell state
__device__ float g_gpart[GSPLIT * BB * NGATE];       // gates partials
__device__ float g_dpart[OSPLIT * BB * EMBD];        // out-proj partials
__device__ float g_dec[BB * EMBD];                   // out-projection result
__device__ float g_scores[BB * SS];                  // attention scores

// ---------------------------------------------------------------------------
// Double-buffered SGEMM:  C[M,N] = A[M,K]*B[N,K]^T
// Block tile 64x64, TK=32, 256 threads, 4x4 micro-tile, float4 everywhere.
// blockIdx.x -> N tile, blockIdx.y -> M tile, blockIdx.z -> split-K slice.
// Requires: lda/ldb/kLen multiples of 4, kLen % 32 == 0, M,N multiples of 64.
// ---------------------------------------------------------------------------
__global__ void __launch_bounds__(256)
sgemm64(const float* __restrict__ A, int lda,
        const float* __restrict__ B, int ldb,
        float* __restrict__ C, size_t ldc, size_t splitStride, int kLen)
{
    constexpr int TM = 64, TN = 64, TK = 32;
    __shared__ float As[2][TK][TM + 4];
    __shared__ float Bs[2][TK][TN + 4];

    const int tid = threadIdx.x;
    const int m0  = blockIdx.y * TM;
    const int n0  = blockIdx.x * TN;

    A += (size_t)m0 * lda + (size_t)blockIdx.z * kLen;
    B += (size_t)n0 * ldb + (size_t)blockIdx.z * kLen;
    C += (size_t)blockIdx.z * splitStride + (size_t)m0 * ldc + n0;

    const int lr  = tid >> 2;        // loader row 0..63
    const int lc4 = tid & 3;         // loader float4 col 0..3 (+4 for 2nd)
    const int tx  = tid & 15;        // n-group
    const int ty  = tid >> 4;        // m-group

    const float* Ald = A + (size_t)lr * lda + lc4 * 4;
    const float* Bld = B + (size_t)lr * ldb + lc4 * 4;

    float4 ra0 = *(const float4*)(Ald);
    float4 ra1 = *(const float4*)(Ald + 16);
    float4 rb0 = *(const float4*)(Bld);
    float4 rb1 = *(const float4*)(Bld + 16);

    float acc[4][4];
#pragma unroll
    for (int i = 0; i < 4; i++)
#pragma unroll
        for (int j = 0; j < 4; j++) acc[i][j] = 0.f;

    const int nk = kLen / TK;
    int buf = 0;

#define STORE_TILE(bf)                                                        \
    {   int kk0 = lc4 * 4;                                                    \
        As[bf][kk0+ 0][lr]=ra0.x; As[bf][kk0+ 1][lr]=ra0.y;                   \
        As[bf][kk0+ 2][lr]=ra0.z; As[bf][kk0+ 3][lr]=ra0.w;                   \
        As[bf][kk0+16][lr]=ra1.x; As[bf][kk0+17][lr]=ra1.y;                   \
        As[bf][kk0+18][lr]=ra1.z; As[bf][kk0+19][lr]=ra1.w;                   \
        Bs[bf][kk0+ 0][lr]=rb0.x; Bs[bf][kk0+ 1][lr]=rb0.y;                   \
        Bs[bf][kk0+ 2][lr]=rb0.z; Bs[bf][kk0+ 3][lr]=rb0.w;                   \
        Bs[bf][kk0+16][lr]=rb1.x; Bs[bf][kk0+17][lr]=rb1.y;                   \
        Bs[bf][kk0+18][lr]=rb1.z; Bs[bf][kk0+19][lr]=rb1.w; }

    STORE_TILE(0);
    __syncthreads();

    for (int kt = 0; kt < nk; kt++) {
        if (kt + 1 < nk) {                      // prefetch next tile to regs
            const float* Ap = Ald + (kt + 1) * TK;
            const float* Bp = Bld + (kt + 1) * TK;
            ra0 = *(const float4*)(Ap);
            ra1 = *(const float4*)(Ap + 16);
            rb0 = *(const float4*)(Bp);
            rb1 = *(const float4*)(Bp + 16);
        }
#pragma unroll
        for (int k = 0; k < TK; k++) {
            float4 a = *(const float4*)&As[buf][k][ty * 4];
            float4 b = *(const float4*)&Bs[buf][k][tx * 4];
            acc[0][0]=fmaf(a.x,b.x,acc[0][0]); acc[0][1]=fmaf(a.x,b.y,acc[0][1]);
            acc[0][2]=fmaf(a.x,b.z,acc[0][2]); acc[0][3]=fmaf(a.x,b.w,acc[0][3]);
            acc[1][0]=fmaf(a.y,b.x,acc[1][0]); acc[1][1]=fmaf(a.y,b.y,acc[1][1]);
            acc[1][2]=fmaf(a.y,b.z,acc[1][2]); acc[1][3]=fmaf(a.y,b.w,acc[1][3]);
            acc[2][0]=fmaf(a.z,b.x,acc[2][0]); acc[2][1]=fmaf(a.z,b.y,acc[2][1]);
            acc[2][2]=fmaf(a.z,b.z,acc[2][2]); acc[2][3]=fmaf(a.z,b.w,acc[2][3]);
            acc[3][0]=fmaf(a.w,b.x,acc[3][0]); acc[3][1]=fmaf(a.w,b.y,acc[3][1]);
            acc[3][2]=fmaf(a.w,b.z,acc[3][2]); acc[3][3]=fmaf(a.w,b.w,acc[3][3]);
        }
        if (kt + 1 < nk) {
            __syncthreads();
            STORE_TILE(buf ^ 1);
            __syncthreads();
            buf ^= 1;
        }
    }
#undef STORE_TILE

#pragma unroll
    for (int i = 0; i < 4; i++) {
        float4 o = make_float4(acc[i][0], acc[i][1], acc[i][2], acc[i][3]);
        *(float4*)(C + (size_t)(ty * 4 + i) * ldc + tx * 4) = o;
    }
}

// ---------------------------------------------------------------------------
// Setup kernels
// ---------------------------------------------------------------------------
__global__ void build_wcat(const float* __restrict__ W_ih,
                           const float* __restrict__ W_hh)
{
    size_t total = (size_t)NGATE * KCAT;
    for (size_t i = (size_t)blockIdx.x * blockDim.x + threadIdx.x; i < total;
         i += (size_t)gridDim.x * blockDim.x) {
        int j = (int)(i / KCAT);
        int k = (int)(i % KCAT);
        g_wcat[i] = (k < EMBD) ? W_ih[(size_t)j * EMBD + k]
                               : W_hh[(size_t)j * HH + (k - EMBD)];
    }
}

__global__ void init_state(const float* __restrict__ dec_init)
{
    int idx = blockIdx.x * blockDim.x + threadIdx.x;   // B*H
    int b = idx >> 10, j = idx & 1023;
    float h0 = dec_init[idx];
    g_hc[b * 2048 + j] = h0;
    g_xcat[b * KCAT + EMBD + j] = h0;
    g_c[idx] = dec_init[BB * HH + idx];
    if (j < EMBD) g_xcat[b * KCAT + j] = 0.f;
}

// ---------------------------------------------------------------------------
// LSTM cell: sum GSPLIT gate partials + bias, apply nonlinearity
// ---------------------------------------------------------------------------
__device__ __forceinline__ float sigf(float x) { return 1.f / (1.f + expf(-x)); }

__global__ void lstm_cell(const float* __restrict__ b_lstm)
{
    int idx = blockIdx.x * blockDim.x + threadIdx.x;   // B*H
    int b = idx >> 10, j = idx & 1023;
    const float* gp = g_gpart + (size_t)b * NGATE;
    const size_t SP = (size_t)BB * NGATE;
    float ig = b_lstm[j], fg = b_lstm[1024 + j],
          gg = b_lstm[2048 + j], og = b_lstm[3072 + j];
#pragma unroll
    for (int s = 0; s < GSPLIT; s++) {
        ig += gp[s * SP + j];
        fg += gp[s * SP + 1024 + j];
        gg += gp[s * SP + 2048 + j];
        og += gp[s * SP + 3072 + j];
    }
    float c = sigf(fg) * g_c[idx] + sigf(ig) * tanhf(gg);
    float h = sigf(og) * tanhf(c);
    g_c[idx] = c;
    g_hc[b * 2048 + j] = h;
    g_xcat[b * KCAT + EMBD + j] = h;
}

// ---------------------------------------------------------------------------
// Attention scores: grid (4, B); each block does 32 rows of keys . h
// ---------------------------------------------------------------------------
__global__ void __launch_bounds__(256)
attn_scores()
{
    int b = blockIdx.y;
    int tid = threadIdx.x, warp = tid >> 5, lane = tid & 31;
    __shared__ float4 sh4[HH / 4];

    const float4* h4 = (const float4*)&g_hc[b * 2048];
    sh4[tid] = h4[tid];                       // 256 float4 = 1024 floats
    __syncthreads();

#pragma unroll
    for (int r = 0; r < 4; r++) {
        int s = blockIdx.x * 32 + warp * 4 + r;
        const float4* k4 = (const float4*)&g_keys[((size_t)b * SS + s) * HH];
        float acc = 0.f;
#pragma unroll
        for (int i = 0; i < 8; i++) {
            float4 kv = k4[lane + 32 * i];
            float4 hv = sh4[lane + 32 * i];
            acc = fmaf(kv.x, hv.x, acc);
            acc = fmaf(kv.y, hv.y, acc);
            acc = fmaf(kv.z, hv.z, acc);
            acc = fmaf(kv.w, hv.w, acc);
        }
#pragma unroll
        for (int o = 16; o; o >>= 1) acc += __shfl_xor_sync(0xffffffffu, acc, o);
        if (lane == 0) g_scores[b * SS + s] = acc;
    }
}

// ---------------------------------------------------------------------------
// Attention context (softmax fused, recomputed per block): grid (4, B)
// Each block computes 256 dims of c_t for batch b.
// ---------------------------------------------------------------------------
__global__ void __launch_bounds__(256)
attn_context(const float* __restrict__ enc, const int* __restrict__ enc_len)
{
    int b = blockIdx.y, e0 = blockIdx.x * 256;
    int tid = threadIdx.x, warp = tid >> 5, lane = tid & 31;
    __shared__ float sa[SS];
    __shared__ float red[8];
    __shared__ float bc;

    int len = enc_len[b];
    float v = -1e9f;
    if (tid < SS) {
        float s = g_scores[b * SS + tid];
        v = (tid < len) ? s : -1e9f;
        sa[tid] = v;
    }
    // block max over 128 entries (warps 0-3 hold them)
    float m = v;
#pragma unroll
    for (int o = 16; o; o >>= 1) m = fmaxf(m, __shfl_xor_sync(0xffffffffu, m, o));
    if (lane == 0) red[warp] = m;
    __syncthreads();
    if (tid == 0) {
        float mm = red[0];
        for (int i = 1; i < 4; i++) mm = fmaxf(mm, red[i]);
        bc = mm;
    }
    __syncthreads();
    float mx = bc;

    float e = (tid < SS) ? expf(v - mx) : 0.f;   // exp(-1e9-mx)==0 exactly
    float s2 = e;
#pragma unroll
    for (int o = 16; o; o >>= 1) s2 += __shfl_xor_sync(0xffffffffu, s2, o);
    __syncthreads();
    if (lane == 0) red[warp] = s2;
    __syncthreads();
    if (tid == 0) bc = red[0] + red[1] + red[2] + red[3];
    __syncthreads();
    float inv = 1.f / bc;
    if (tid < SS) sa[tid] = e * inv;
    __syncthreads();

    const float* ep = enc + ((size_t)b * SS) * EE + e0 + tid;
    float acc = 0.f;
    int s = 0;
    for (; s + 4 <= len; s += 4) {
        float x0 = ep[(size_t)(s + 0) * EE];
        float x1 = ep[(size_t)(s + 1) * EE];
        float x2 = ep[(size_t)(s + 2) * EE];
        float x3 = ep[(size_t)(s + 3) * EE];
        acc = fmaf(sa[s + 0], x0, acc);
        acc = fmaf(sa[s + 1], x1, acc);
        acc = fmaf(sa[s + 2], x2, acc);
        acc = fmaf(sa[s + 3], x3, acc);
    }
    for (; s < len; s++) acc = fmaf(sa[s], ep[(size_t)s * EE], acc);
    g_hc[b * 2048 + HH + e0 + tid] = acc;
}

// ---------------------------------------------------------------------------
// Reduce out-projection split-K partials
// ---------------------------------------------------------------------------
__global__ void reduce_dec()
{
    int idx = blockIdx.x * blockDim.x + threadIdx.x;   // B*EMBD = 32768
    float a = 0.f;
#pragma unroll
    for (int s = 0; s < OSPLIT; s++) a += g_dpart[(size_t)s * BB * EMBD + idx];
    g_dec[idx] = a;
}

// ---------------------------------------------------------------------------
// Greedy argmax over logits row + embedding gather
// ---------------------------------------------------------------------------
__global__ void __launch_bounds__(1024)
argmax_embed(const float* __restrict__ logits, const float* __restrict__ emb, int t)
{
    int b = blockIdx.x;
    const float4* row4 = (const float4*)(logits + ((size_t)b * TT + t) * VV);
    int tid = threadIdx.x;

    float bv = -INFINITY;
    int   bi = 0x7fffffff;
#pragma unroll
    for (int j = 0; j < 8; j++) {
        int v4 = j * 1024 + tid;
        if (v4 < VV / 4) {
            float4 x = row4[v4];
            int base = v4 * 4;
            if (x.x > bv || (x.x == bv && base     < bi)) { bv = x.x; bi = base;     }
            if (x.y > bv || (x.y == bv && base + 1 < bi)) { bv = x.y; bi = base + 1; }
            if (x.z > bv || (x.z == bv && base + 2 < bi)) { bv = x.z; bi = base + 2; }
            if (x.w > bv || (x.w == bv && base + 3 < bi)) { bv = x.w; bi = base + 3; }
        }
    }
#pragma unroll
    for (int o = 16; o; o >>= 1) {
        float ov = __shfl_xor_sync(0xffffffffu, bv, o);
        int   oi = __shfl_xor_sync(0xffffffffu, bi, o);
        if (ov > bv || (ov == bv && oi < bi)) { bv = ov; bi = oi; }
    }
    __shared__ float sv[32];
    __shared__ int   si[32];
    __shared__ int   ssym;
    int warp = tid >> 5, lane = tid & 31;
    if (lane == 0) { sv[warp] = bv; si[warp] = bi; }
    __syncthreads();
    if (warp == 0) {
        bv = sv[lane]; bi = si[lane];
#pragma unroll
        for (int o = 16; o; o >>= 1) {
            float ov = __shfl_xor_sync(0xffffffffu, bv, o);
            int   oi = __shfl_xor_sync(0xffffffffu, bi, o);
            if (ov > bv || (ov == bv && oi < bi)) { bv = ov; bi = oi; }
        }
        if (lane == 0) ssym = bi;
    }
    __syncthreads();
    int sym = ssym;
    if (tid < EMBD / 4) {
        const float4* er = (const float4*)(emb + (size_t)sym * EMBD);
        ((float4*)&g_xcat[b * KCAT])[tid] = er[tid];
    }
}

// ---------------------------------------------------------------------------
// Fused in-place log-softmax over each [VV] row of d_out
// ---------------------------------------------------------------------------
__global__ void __launch_bounds__(1024)
logsoftmax_rows(float* __restrict__ out)
{
    float* p = out + (size_t)blockIdx.x * VV;
    int tid = threadIdx.x;

    float x[32];
    float mx = -INFINITY;
#pragma unroll
    for (int i = 0; i < 32; i++) {
        int v = tid + (i << 10);
        x[i] = (v < VV) ? p[v] : -INFINITY;
        mx = fmaxf(mx, x[i]);
    }
    __shared__ float red[32];
    __shared__ float bc;
#pragma unroll
    for (int o = 16; o; o >>= 1) mx = fmaxf(mx, __shfl_xor_sync(0xffffffffu, mx, o));
    if ((tid & 31) == 0) red[tid >> 5] = mx;
    __syncthreads();
    if (tid < 32) {
        float m = red[tid];
#pragma unroll
        for (int o = 16; o; o >>= 1) m = fmaxf(m, __shfl_xor_sync(0xffffffffu, m, o));
        if (tid == 0) bc = m;
    }
    __syncthreads();
    float M = bc;

    float s = 0.f;
#pragma unroll
    for (int i = 0; i < 32; i++) s += expf(x[i] - M);
    __syncthreads();
#pragma unroll
    for (int o = 16; o; o >>= 1) s += __shfl_xor_sync(0xffffffffu, s, o);
    if ((tid & 31) == 0) red[tid >> 5] = s;
    __syncthreads();
    if (tid < 32) {
        float m = red[tid];
#pragma unroll
        for (int o = 16; o; o >>= 1) m += __shfl_xor_sync(0xffffffffu, m, o);
        if (tid == 0) bc = m;
    }
    __syncthreads();
    float lz = M + logf(bc);
#pragma unroll
    for (int i = 0; i < 32; i++) {
        int v = tid + (i << 10);
        if (v < VV) p[v] = x[i] - lz;
    }
}

__global__ void fill_tail(float* __restrict__ p, long n, float val)
{
    long i = (long)blockIdx.x * blockDim.x + threadIdx.x;
    if (i < n) p[i] = val;
}

// ---------------------------------------------------------------------------
// Launch
// ---------------------------------------------------------------------------
extern "C" void kernel_launch(void* const* d_in, const int* in_sizes, int n_in,
                              void* d_out, int out_size)
{
    const float* dec_init  = (const float*)d_in[0];
    const float* enc       = (const float*)d_in[1];
    const int*   enc_len   = (const int*)d_in[2];
    /* d_in[3] = tgt (unused in eval mode) */
    const float* W_ih      = (const float*)d_in[4];
    const float* W_hh      = (const float*)d_in[5];
    const float* b_lstm    = (const float*)d_in[6];
    const float* W_attproj = (const float*)d_in[7];
    const float* W_out     = (const float*)d_in[8];
    const float* W_vocab   = (const float*)d_in[9];
    const float* emb       = (const float*)d_in[10];
    float* out = (float*)d_out;

    void *p_keys, *p_wcat, *p_xcat, *p_hc, *p_gpart, *p_dpart, *p_dec;
    cudaGetSymbolAddress(&p_keys,  g_keys);
    cudaGetSymbolAddress(&p_wcat,  g_wcat);
    cudaGetSymbolAddress(&p_xcat,  g_xcat);
    cudaGetSymbolAddress(&p_hc,    g_hc);
    cudaGetSymbolAddress(&p_gpart, g_gpart);
    cudaGetSymbolAddress(&p_dpart, g_dpart);
    cudaGetSymbolAddress(&p_dec,   g_dec);

    // one-time setup
    build_wcat<<<2048, 256>>>(W_ih, W_hh);
    init_state<<<(BB * HH) / 256, 256>>>(dec_init);
    // keys[B*S, H] = enc[B*S, E] @ W_attproj^T   (2048 blocks)
    sgemm64<<<dim3(HH / 64, (BB * SS) / 64, 1), 256>>>(
        enc, EE, W_attproj, EE, (float*)p_keys, HH, 0, EE);

    for (int t = 0; t < TT; t++) {
        // gates partials: split-K x4  (256 blocks)
        sgemm64<<<dim3(NGATE / 64, 1, GSPLIT), 256>>>(
            (const float*)p_xcat, KCAT, (const float*)p_wcat, KCAT,
            (float*)p_gpart, NGATE, (size_t)BB * NGATE, KCAT / GSPLIT);
        lstm_cell<<<(BB * HH) / 256, 256>>>(b_lstm);
        attn_scores<<<dim3(4, BB), 256>>>();
        attn_context<<<dim3(4, BB), 256>>>(enc, enc_len);
        // dec partials: split-K x16  (128 blocks)
        sgemm64<<<dim3(EMBD / 64, 1, OSPLIT), 256>>>(
            (const float*)p_hc, 2048, W_out, 2048,
            (float*)p_dpart, EMBD, (size_t)BB * EMBD, 2048 / OSPLIT);
        reduce_dec<<<(BB * EMBD) / 256, 256>>>();
        // vocab logits straight into d_out[b, t, :]  (500 blocks)
        sgemm64<<<dim3(VV / 64, 1, 1), 256>>>(
            (const float*)p_dec, EMBD, W_vocab, EMBD,
            out + (size_t)t * VV, (size_t)TT * VV, 0, EMBD);
        argmax_embed<<<BB, 1024>>>(out, emb, t);
    }

    // final log-softmax in place over all B*T rows
    logsoftmax_rows<<<BB * TT, 1024>>>(out);

    // tgt_len output: always T (== 50) per the reference's final where()
    long extra = (long)out_size - (long)BB * TT * VV;
    if (extra > 0)
        fill_tail<<<(unsigned)((extra + 255) / 256), 256>>>(
            out + (size_t)BB * TT * VV, extra, 50.0f);
}

// round 8
// speedup vs baseline: 2.8038x; 1.1351x over previous
#include <cuda_runtime.h>
#include <math.h>

// Problem constants (fixed by the reference)
#define BB   64
#define SS   128
#define HH   1024
#define EE   1024
#define EMBD 512
#define VV   32000
#define TT   50
#define KCAT 1536          // EMBD + HH
#define NGATE 4096         // 4*HH
#define GSPLIT 8           // split-K for gates GEMM (KCAT/8 = 192)
#define OSPLIT 32          // split-K for out-projection GEMM (2048/32 = 64)

// ---------------------------------------------------------------------------
// Device scratch (static device globals — no allocation)
// ---------------------------------------------------------------------------
__device__ float g_keys[(size_t)BB * SS * HH];       // att keys [B,S,H]
__device__ float g_wcat[(size_t)NGATE * KCAT];       // [W_ih | W_hh]
__device__ float g_xcat[BB * KCAT];                  // [prev_emb | h]
__device__ float g_hc[BB * 2048];                    // [h | c_t]
__device__ float g_c[BB * HH];                       // LSTM cell state
__device__ float g_gpart[GSPLIT * BB * NGATE];       // gates partials
__device__ float g_dpart[OSPLIT * BB * EMBD];        // out-proj partials
__device__ float g_dec[BB * EMBD];                   // out-projection result
__device__ float g_scores[BB * SS];                  // attention scores

// ---------------------------------------------------------------------------
// High-throughput SGEMM:  C[M,N] = A[M,K]*B[N,K]^T
// Block tile 64x128, TK=32, 256 threads, 8x4 micro-tile.
//   - A smem reads: warp-uniform (broadcast, conflict-free)
//   - B smem reads: lane*16B contiguous (conflict-free LDS.128)
// blockIdx.x -> N tile, blockIdx.y -> M tile, blockIdx.z -> split-K slice.
// Requires: kLen % 32 == 0, M mult of 64, N mult of 128, lda/ldb mult of 4.
// ---------------------------------------------------------------------------
__global__ void __launch_bounds__(256)
sgemm128(const float* __restrict__ A, int lda,
         const float* __restrict__ B, int ldb,
         float* __restrict__ C, size_t ldc, size_t splitStride, int kLen)
{
    constexpr int TM = 64, TN = 128, TK = 32;
    __shared__ float As[2][TK][TM + 4];
    __shared__ float Bs[2][TK][TN + 4];

    const int tid = threadIdx.x;
    const int m0  = blockIdx.y * TM;
    const int n0  = blockIdx.x * TN;

    A += (size_t)m0 * lda + (size_t)blockIdx.z * kLen;
    B += (size_t)n0 * ldb + (size_t)blockIdx.z * kLen;
    C += (size_t)blockIdx.z * splitStride + (size_t)m0 * ldc + n0;

    // loaders
    const int ar = tid >> 2;            // A row 0..63
    const int ak = (tid & 3) * 4;       // A k base {0,4,8,12} (+16)
    const int br = tid >> 1;            // B row 0..127
    const int bk = (tid & 1) * 4;       // B k base {0,4} (+8,+16,+24)
    const float* Ald = A + (size_t)ar * lda + ak;
    const float* Bld = B + (size_t)br * ldb + bk;

    float4 ra0 = *(const float4*)(Ald);
    float4 ra1 = *(const float4*)(Ald + 16);
    float4 rb0 = *(const float4*)(Bld);
    float4 rb1 = *(const float4*)(Bld + 8);
    float4 rb2 = *(const float4*)(Bld + 16);
    float4 rb3 = *(const float4*)(Bld + 24);

    // compute mapping: 8 rows x 4 cols per thread
    const int rg = tid >> 5;            // warp id 0..7  -> rows rg*8..rg*8+7
    const int cg = tid & 31;            // lane          -> cols cg*4..cg*4+3

    float acc[8][4];
#pragma unroll
    for (int i = 0; i < 8; i++)
#pragma unroll
        for (int j = 0; j < 4; j++) acc[i][j] = 0.f;

    const int nk = kLen / TK;
    int buf = 0;

#define STORE_TILE128(bf)                                                     \
    {   As[bf][ak+ 0][ar]=ra0.x; As[bf][ak+ 1][ar]=ra0.y;                     \
        As[bf][ak+ 2][ar]=ra0.z; As[bf][ak+ 3][ar]=ra0.w;                     \
        As[bf][ak+16][ar]=ra1.x; As[bf][ak+17][ar]=ra1.y;                     \
        As[bf][ak+18][ar]=ra1.z; As[bf][ak+19][ar]=ra1.w;                     \
        Bs[bf][bk+ 0][br]=rb0.x; Bs[bf][bk+ 1][br]=rb0.y;                     \
        Bs[bf][bk+ 2][br]=rb0.z; Bs[bf][bk+ 3][br]=rb0.w;                     \
        Bs[bf][bk+ 8][br]=rb1.x; Bs[bf][bk+ 9][br]=rb1.y;                     \
        Bs[bf][bk+10][br]=rb1.z; Bs[bf][bk+11][br]=rb1.w;                     \
        Bs[bf][bk+16][br]=rb2.x; Bs[bf][bk+17][br]=rb2.y;                     \
        Bs[bf][bk+18][br]=rb2.z; Bs[bf][bk+19][br]=rb2.w;                     \
        Bs[bf][bk+24][br]=rb3.x; Bs[bf][bk+25][br]=rb3.y;                     \
        Bs[bf][bk+26][br]=rb3.z; Bs[bf][bk+27][br]=rb3.w; }

    STORE_TILE128(0);
    __syncthreads();

    for (int kt = 0; kt < nk; kt++) {
        if (kt + 1 < nk) {                      // prefetch next tile to regs
            const float* Ap = Ald + (kt + 1) * TK;
            const float* Bp = Bld + (kt + 1) * TK;
            ra0 = *(const float4*)(Ap);
            ra1 = *(const float4*)(Ap + 16);
            rb0 = *(const float4*)(Bp);
            rb1 = *(const float4*)(Bp + 8);
            rb2 = *(const float4*)(Bp + 16);
            rb3 = *(const float4*)(Bp + 24);
        }
#pragma unroll
        for (int k = 0; k < TK; k++) {
            float4 a0 = *(const float4*)&As[buf][k][rg * 8];      // broadcast
            float4 a1 = *(const float4*)&As[buf][k][rg * 8 + 4];  // broadcast
            float4 b  = *(const float4*)&Bs[buf][k][cg * 4];      // conflict-free
            acc[0][0]=fmaf(a0.x,b.x,acc[0][0]); acc[0][1]=fmaf(a0.x,b.y,acc[0][1]);
            acc[0][2]=fmaf(a0.x,b.z,acc[0][2]); acc[0][3]=fmaf(a0.x,b.w,acc[0][3]);
            acc[1][0]=fmaf(a0.y,b.x,acc[1][0]); acc[1][1]=fmaf(a0.y,b.y,acc[1][1]);
            acc[1][2]=fmaf(a0.y,b.z,acc[1][2]); acc[1][3]=fmaf(a0.y,b.w,acc[1][3]);
            acc[2][0]=fmaf(a0.z,b.x,acc[2][0]); acc[2][1]=fmaf(a0.z,b.y,acc[2][1]);
            acc[2][2]=fmaf(a0.z,b.z,acc[2][2]); acc[2][3]=fmaf(a0.z,b.w,acc[2][3]);
            acc[3][0]=fmaf(a0.w,b.x,acc[3][0]); acc[3][1]=fmaf(a0.w,b.y,acc[3][1]);
            acc[3][2]=fmaf(a0.w,b.z,acc[3][2]); acc[3][3]=fmaf(a0.w,b.w,acc[3][3]);
            acc[4][0]=fmaf(a1.x,b.x,acc[4][0]); acc[4][1]=fmaf(a1.x,b.y,acc[4][1]);
            acc[4][2]=fmaf(a1.x,b.z,acc[4][2]); acc[4][3]=fmaf(a1.x,b.w,acc[4][3]);
            acc[5][0]=fmaf(a1.y,b.x,acc[5][0]); acc[5][1]=fmaf(a1.y,b.y,acc[5][1]);
            acc[5][2]=fmaf(a1.y,b.z,acc[5][2]); acc[5][3]=fmaf(a1.y,b.w,acc[5][3]);
            acc[6][0]=fmaf(a1.z,b.x,acc[6][0]); acc[6][1]=fmaf(a1.z,b.y,acc[6][1]);
            acc[6][2]=fmaf(a1.z,b.z,acc[6][2]); acc[6][3]=fmaf(a1.z,b.w,acc[6][3]);
            acc[7][0]=fmaf(a1.w,b.x,acc[7][0]); acc[7][1]=fmaf(a1.w,b.y,acc[7][1]);
            acc[7][2]=fmaf(a1.w,b.z,acc[7][2]); acc[7][3]=fmaf(a1.w,b.w,acc[7][3]);
        }
        if (kt + 1 < nk) {
            __syncthreads();
            STORE_TILE128(buf ^ 1);
            __syncthreads();
            buf ^= 1;
        }
    }
#undef STORE_TILE128

#pragma unroll
    for (int i = 0; i < 8; i++) {
        float4 o = make_float4(acc[i][0], acc[i][1], acc[i][2], acc[i][3]);
        *(float4*)(C + (size_t)(rg * 8 + i) * ldc + cg * 4) = o;   // coalesced
    }
}

// ---------------------------------------------------------------------------
// Small SGEMM (TN=64, 4x4 micro-tile) — used only for the tiny out-projection
// ---------------------------------------------------------------------------
__global__ void __launch_bounds__(256)
sgemm64(const float* __restrict__ A, int lda,
        const float* __restrict__ B, int ldb,
        float* __restrict__ C, size_t ldc, size_t splitStride, int kLen)
{
    constexpr int TM = 64, TN = 64, TK = 32;
    __shared__ float As[2][TK][TM + 4];
    __shared__ float Bs[2][TK][TN + 4];

    const int tid = threadIdx.x;
    const int m0  = blockIdx.y * TM;
    const int n0  = blockIdx.x * TN;

    A += (size_t)m0 * lda + (size_t)blockIdx.z * kLen;
    B += (size_t)n0 * ldb + (size_t)blockIdx.z * kLen;
    C += (size_t)blockIdx.z * splitStride + (size_t)m0 * ldc + n0;

    const int lr  = tid >> 2;
    const int lc4 = tid & 3;
    const int tx  = tid & 15;
    const int ty  = tid >> 4;

    const float* Ald = A + (size_t)lr * lda + lc4 * 4;
    const float* Bld = B + (size_t)lr * ldb + lc4 * 4;

    float4 ra0 = *(const float4*)(Ald);
    float4 ra1 = *(const float4*)(Ald + 16);
    float4 rb0 = *(const float4*)(Bld);
    float4 rb1 = *(const float4*)(Bld + 16);

    float acc[4][4];
#pragma unroll
    for (int i = 0; i < 4; i++)
#pragma unroll
        for (int j = 0; j < 4; j++) acc[i][j] = 0.f;

    const int nk = kLen / TK;
    int buf = 0;

#define STORE_TILE(bf)                                                        \
    {   int kk0 = lc4 * 4;                                                    \
        As[bf][kk0+ 0][lr]=ra0.x; As[bf][kk0+ 1][lr]=ra0.y;                   \
        As[bf][kk0+ 2][lr]=ra0.z; As[bf][kk0+ 3][lr]=ra0.w;                   \
        As[bf][kk0+16][lr]=ra1.x; As[bf][kk0+17][lr]=ra1.y;                   \
        As[bf][kk0+18][lr]=ra1.z; As[bf][kk0+19][lr]=ra1.w;                   \
        Bs[bf][kk0+ 0][lr]=rb0.x; Bs[bf][kk0+ 1][lr]=rb0.y;                   \
        Bs[bf][kk0+ 2][lr]=rb0.z; Bs[bf][kk0+ 3][lr]=rb0.w;                   \
        Bs[bf][kk0+16][lr]=rb1.x; Bs[bf][kk0+17][lr]=rb1.y;                   \
        Bs[bf][kk0+18][lr]=rb1.z; Bs[bf][kk0+19][lr]=rb1.w; }

    STORE_TILE(0);
    __syncthreads();

    for (int kt = 0; kt < nk; kt++) {
        if (kt + 1 < nk) {
            const float* Ap = Ald + (kt + 1) * TK;
            const float* Bp = Bld + (kt + 1) * TK;
            ra0 = *(const float4*)(Ap);
            ra1 = *(const float4*)(Ap + 16);
            rb0 = *(const float4*)(Bp);
            rb1 = *(const float4*)(Bp + 16);
        }
#pragma unroll
        for (int k = 0; k < TK; k++) {
            float4 a = *(const float4*)&As[buf][k][ty * 4];
            float4 b = *(const float4*)&Bs[buf][k][tx * 4];
            acc[0][0]=fmaf(a.x,b.x,acc[0][0]); acc[0][1]=fmaf(a.x,b.y,acc[0][1]);
            acc[0][2]=fmaf(a.x,b.z,acc[0][2]); acc[0][3]=fmaf(a.x,b.w,acc[0][3]);
            acc[1][0]=fmaf(a.y,b.x,acc[1][0]); acc[1][1]=fmaf(a.y,b.y,acc[1][1]);
            acc[1][2]=fmaf(a.y,b.z,acc[1][2]); acc[1][3]=fmaf(a.y,b.w,acc[1][3]);
            acc[2][0]=fmaf(a.z,b.x,acc[2][0]); acc[2][1]=fmaf(a.z,b.y,acc[2][1]);
            acc[2][2]=fmaf(a.z,b.z,acc[2][2]); acc[2][3]=fmaf(a.z,b.w,acc[2][3]);
            acc[3][0]=fmaf(a.w,b.x,acc[3][0]); acc[3][1]=fmaf(a.w,b.y,acc[3][1]);
            acc[3][2]=fmaf(a.w,b.z,acc[3][2]); acc[3][3]=fmaf(a.w,b.w,acc[3][3]);
        }
        if (kt + 1 < nk) {
            __syncthreads();
            STORE_TILE(buf ^ 1);
            __syncthreads();
            buf ^= 1;
        }
    }
#undef STORE_TILE

#pragma unroll
    for (int i = 0; i < 4; i++) {
        float4 o = make_float4(acc[i][0], acc[i][1], acc[i][2], acc[i][3]);
        *(float4*)(C + (size_t)(ty * 4 + i) * ldc + tx * 4) = o;
    }
}

// ---------------------------------------------------------------------------
// Setup kernels
// ---------------------------------------------------------------------------
__global__ void build_wcat(const float* __restrict__ W_ih,
                           const float* __restrict__ W_hh)
{
    size_t total = (size_t)NGATE * KCAT;
    for (size_t i = (size_t)blockIdx.x * blockDim.x + threadIdx.x; i < total;
         i += (size_t)gridDim.x * blockDim.x) {
        int j = (int)(i / KCAT);
        int k = (int)(i % KCAT);
        g_wcat[i] = (k < EMBD) ? W_ih[(size_t)j * EMBD + k]
                               : W_hh[(size_t)j * HH + (k - EMBD)];
    }
}

__global__ void init_state(const float* __restrict__ dec_init)
{
    int idx = blockIdx.x * blockDim.x + threadIdx.x;   // B*H
    int b = idx >> 10, j = idx & 1023;
    float h0 = dec_init[idx];
    g_hc[b * 2048 + j] = h0;
    g_xcat[b * KCAT + EMBD + j] = h0;
    g_c[idx] = dec_init[BB * HH + idx];
    if (j < EMBD) g_xcat[b * KCAT + j] = 0.f;
}

// ---------------------------------------------------------------------------
// LSTM cell: sum GSPLIT gate partials + bias, apply nonlinearity
// ---------------------------------------------------------------------------
__device__ __forceinline__ float sigf(float x) { return 1.f / (1.f + expf(-x)); }

__global__ void lstm_cell(const float* __restrict__ b_lstm)
{
    int idx = blockIdx.x * blockDim.x + threadIdx.x;   // B*H
    int b = idx >> 10, j = idx & 1023;
    const float* gp = g_gpart + (size_t)b * NGATE;
    const size_t SP = (size_t)BB * NGATE;
    float ig = b_lstm[j], fg = b_lstm[1024 + j],
          gg = b_lstm[2048 + j], og = b_lstm[3072 + j];
#pragma unroll
    for (int s = 0; s < GSPLIT; s++) {
        ig += gp[s * SP + j];
        fg += gp[s * SP + 1024 + j];
        gg += gp[s * SP + 2048 + j];
        og += gp[s * SP + 3072 + j];
    }
    float c = sigf(fg) * g_c[idx] + sigf(ig) * tanhf(gg);
    float h = sigf(og) * tanhf(c);
    g_c[idx] = c;
    g_hc[b * 2048 + j] = h;
    g_xcat[b * KCAT + EMBD + j] = h;
}

// ---------------------------------------------------------------------------
// Attention scores: grid (4, B); each block does 32 rows of keys . h
// ---------------------------------------------------------------------------
__global__ void __launch_bounds__(256)
attn_scores()
{
    int b = blockIdx.y;
    int tid = threadIdx.x, warp = tid >> 5, lane = tid & 31;
    __shared__ float4 sh4[HH / 4];

    const float4* h4 = (const float4*)&g_hc[b * 2048];
    sh4[tid] = h4[tid];
    __syncthreads();

#pragma unroll
    for (int r = 0; r < 4; r++) {
        int s = blockIdx.x * 32 + warp * 4 + r;
        const float4* k4 = (const float4*)&g_keys[((size_t)b * SS + s) * HH];
        float acc = 0.f;
#pragma unroll
        for (int i = 0; i < 8; i++) {
            float4 kv = k4[lane + 32 * i];
            float4 hv = sh4[lane + 32 * i];
            acc = fmaf(kv.x, hv.x, acc);
            acc = fmaf(kv.y, hv.y, acc);
            acc = fmaf(kv.z, hv.z, acc);
            acc = fmaf(kv.w, hv.w, acc);
        }
#pragma unroll
        for (int o = 16; o; o >>= 1) acc += __shfl_xor_sync(0xffffffffu, acc, o);
        if (lane == 0) g_scores[b * SS + s] = acc;
    }
}

// ---------------------------------------------------------------------------
// Attention context (softmax fused, recomputed per block): grid (4, B)
// ---------------------------------------------------------------------------
__global__ void __launch_bounds__(256)
attn_context(const float* __restrict__ enc, const int* __restrict__ enc_len)
{
    int b = blockIdx.y, e0 = blockIdx.x * 256;
    int tid = threadIdx.x, warp = tid >> 5, lane = tid & 31;
    __shared__ float sa[SS];
    __shared__ float red[8];
    __shared__ float bc;

    int len = enc_len[b];
    float v = -1e9f;
    if (tid < SS) {
        float s = g_scores[b * SS + tid];
        v = (tid < len) ? s : -1e9f;
        sa[tid] = v;
    }
    float m = v;
#pragma unroll
    for (int o = 16; o; o >>= 1) m = fmaxf(m, __shfl_xor_sync(0xffffffffu, m, o));
    if (lane == 0) red[warp] = m;
    __syncthreads();
    if (tid == 0) {
        float mm = red[0];
        for (int i = 1; i < 4; i++) mm = fmaxf(mm, red[i]);
        bc = mm;
    }
    __syncthreads();
    float mx = bc;

    float e = (tid < SS) ? expf(v - mx) : 0.f;
    float s2 = e;
#pragma unroll
    for (int o = 16; o; o >>= 1) s2 += __shfl_xor_sync(0xffffffffu, s2, o);
    __syncthreads();
    if (lane == 0) red[warp] = s2;
    __syncthreads();
    if (tid == 0) bc = red[0] + red[1] + red[2] + red[3];
    __syncthreads();
    float inv = 1.f / bc;
    if (tid < SS) sa[tid] = e * inv;
    __syncthreads();

    const float* ep = enc + ((size_t)b * SS) * EE + e0 + tid;
    float acc = 0.f;
    int s = 0;
    for (; s + 4 <= len; s += 4) {
        float x0 = ep[(size_t)(s + 0) * EE];
        float x1 = ep[(size_t)(s + 1) * EE];
        float x2 = ep[(size_t)(s + 2) * EE];
        float x3 = ep[(size_t)(s + 3) * EE];
        acc = fmaf(sa[s + 0], x0, acc);
        acc = fmaf(sa[s + 1], x1, acc);
        acc = fmaf(sa[s + 2], x2, acc);
        acc = fmaf(sa[s + 3], x3, acc);
    }
    for (; s < len; s++) acc = fmaf(sa[s], ep[(size_t)s * EE], acc);
    g_hc[b * 2048 + HH + e0 + tid] = acc;
}

// ---------------------------------------------------------------------------
// Reduce out-projection split-K partials
// ---------------------------------------------------------------------------
__global__ void reduce_dec()
{
    int idx = blockIdx.x * blockDim.x + threadIdx.x;   // B*EMBD
    float a = 0.f;
#pragma unroll
    for (int s = 0; s < OSPLIT; s++) a += g_dpart[(size_t)s * BB * EMBD + idx];
    g_dec[idx] = a;
}

// ---------------------------------------------------------------------------
// Greedy argmax over logits row + embedding gather
// ---------------------------------------------------------------------------
__global__ void __launch_bounds__(1024)
argmax_embed(const float* __restrict__ logits, const float* __restrict__ emb, int t)
{
    int b = blockIdx.x;
    const float4* row4 = (const float4*)(logits + ((size_t)b * TT + t) * VV);
    int tid = threadIdx.x;

    float bv = -INFINITY;
    int   bi = 0x7fffffff;
#pragma unroll
    for (int j = 0; j < 8; j++) {
        int v4 = j * 1024 + tid;
        if (v4 < VV / 4) {
            float4 x = row4[v4];
            int base = v4 * 4;
            if (x.x > bv || (x.x == bv && base     < bi)) { bv = x.x; bi = base;     }
            if (x.y > bv || (x.y == bv && base + 1 < bi)) { bv = x.y; bi = base + 1; }
            if (x.z > bv || (x.z == bv && base + 2 < bi)) { bv = x.z; bi = base + 2; }
            if (x.w > bv || (x.w == bv && base + 3 < bi)) { bv = x.w; bi = base + 3; }
        }
    }
#pragma unroll
    for (int o = 16; o; o >>= 1) {
        float ov = __shfl_xor_sync(0xffffffffu, bv, o);
        int   oi = __shfl_xor_sync(0xffffffffu, bi, o);
        if (ov > bv || (ov == bv && oi < bi)) { bv = ov; bi = oi; }
    }
    __shared__ float sv[32];
    __shared__ int   si[32];
    __shared__ int   ssym;
    int warp = tid >> 5, lane = tid & 31;
    if (lane == 0) { sv[warp] = bv; si[warp] = bi; }
    __syncthreads();
    if (warp == 0) {
        bv = sv[lane]; bi = si[lane];
#pragma unroll
        for (int o = 16; o; o >>= 1) {
            float ov = __shfl_xor_sync(0xffffffffu, bv, o);
            int   oi = __shfl_xor_sync(0xffffffffu, bi, o);
            if (ov > bv || (ov == bv && oi < bi)) { bv = ov; bi = oi; }
        }
        if (lane == 0) ssym = bi;
    }
    __syncthreads();
    int sym = ssym;
    if (tid < EMBD / 4) {
        const float4* er = (const float4*)(emb + (size_t)sym * EMBD);
        ((float4*)&g_xcat[b * KCAT])[tid] = er[tid];
    }
}

// ---------------------------------------------------------------------------
// Fused in-place log-softmax over each [VV] row of d_out
// ---------------------------------------------------------------------------
__global__ void __launch_bounds__(1024)
logsoftmax_rows(float* __restrict__ out)
{
    float* p = out + (size_t)blockIdx.x * VV;
    int tid = threadIdx.x;

    float x[32];
    float mx = -INFINITY;
#pragma unroll
    for (int i = 0; i < 32; i++) {
        int v = tid + (i << 10);
        x[i] = (v < VV) ? p[v] : -INFINITY;
        mx = fmaxf(mx, x[i]);
    }
    __shared__ float red[32];
    __shared__ float bc;
#pragma unroll
    for (int o = 16; o; o >>= 1) mx = fmaxf(mx, __shfl_xor_sync(0xffffffffu, mx, o));
    if ((tid & 31) == 0) red[tid >> 5] = mx;
    __syncthreads();
    if (tid < 32) {
        float m = red[tid];
#pragma unroll
        for (int o = 16; o; o >>= 1) m = fmaxf(m, __shfl_xor_sync(0xffffffffu, m, o));
        if (tid == 0) bc = m;
    }
    __syncthreads();
    float M = bc;

    float s = 0.f;
#pragma unroll
    for (int i = 0; i < 32; i++) s += expf(x[i] - M);
    __syncthreads();
#pragma unroll
    for (int o = 16; o; o >>= 1) s += __shfl_xor_sync(0xffffffffu, s, o);
    if ((tid & 31) == 0) red[tid >> 5] = s;
    __syncthreads();
    if (tid < 32) {
        float m = red[tid];
#pragma unroll
        for (int o = 16; o; o >>= 1) m += __shfl_xor_sync(0xffffffffu, m, o);
        if (tid == 0) bc = m;
    }
    __syncthreads();
    float lz = M + logf(bc);
#pragma unroll
    for (int i = 0; i < 32; i++) {
        int v = tid + (i << 10);
        if (v < VV) p[v] = x[i] - lz;
    }
}

__global__ void fill_tail(float* __restrict__ p, long n, float val)
{
    long i = (long)blockIdx.x * blockDim.x + threadIdx.x;
    if (i < n) p[i] = val;
}

// ---------------------------------------------------------------------------
// Launch
// ---------------------------------------------------------------------------
extern "C" void kernel_launch(void* const* d_in, const int* in_sizes, int n_in,
                              void* d_out, int out_size)
{
    const float* dec_init  = (const float*)d_in[0];
    const float* enc       = (const float*)d_in[1];
    const int*   enc_len   = (const int*)d_in[2];
    /* d_in[3] = tgt (unused in eval mode) */
    const float* W_ih      = (const float*)d_in[4];
    const float* W_hh      = (const float*)d_in[5];
    const float* b_lstm    = (const float*)d_in[6];
    const float* W_attproj = (const float*)d_in[7];
    const float* W_out     = (const float*)d_in[8];
    const float* W_vocab   = (const float*)d_in[9];
    const float* emb       = (const float*)d_in[10];
    float* out = (float*)d_out;

    void *p_keys, *p_wcat, *p_xcat, *p_hc, *p_gpart, *p_dpart, *p_dec;
    cudaGetSymbolAddress(&p_keys,  g_keys);
    cudaGetSymbolAddress(&p_wcat,  g_wcat);
    cudaGetSymbolAddress(&p_xcat,  g_xcat);
    cudaGetSymbolAddress(&p_hc,    g_hc);
    cudaGetSymbolAddress(&p_gpart, g_gpart);
    cudaGetSymbolAddress(&p_dpart, g_dpart);
    cudaGetSymbolAddress(&p_dec,   g_dec);

    // one-time setup
    build_wcat<<<2048, 256>>>(W_ih, W_hh);
    init_state<<<(BB * HH) / 256, 256>>>(dec_init);
    // keys[B*S, H] = enc[B*S, E] @ W_attproj^T   (grid 8 x 128 = 1024 blocks)
    sgemm128<<<dim3(HH / 128, (BB * SS) / 64, 1), 256>>>(
        enc, EE, W_attproj, EE, (float*)p_keys, HH, 0, EE);

    for (int t = 0; t < TT; t++) {
        // gates partials: split-K x8  (32 x 8 = 256 blocks, kLen=192)
        sgemm128<<<dim3(NGATE / 128, 1, GSPLIT), 256>>>(
            (const float*)p_xcat, KCAT, (const float*)p_wcat, KCAT,
            (float*)p_gpart, NGATE, (size_t)BB * NGATE, KCAT / GSPLIT);
        lstm_cell<<<(BB * HH) / 256, 256>>>(b_lstm);
        attn_scores<<<dim3(4, BB), 256>>>();
        attn_context<<<dim3(4, BB), 256>>>(enc, enc_len);
        // dec partials: split-K x32  (8 x 32 = 256 blocks, kLen=64)
        sgemm64<<<dim3(EMBD / 64, 1, OSPLIT), 256>>>(
            (const float*)p_hc, 2048, W_out, 2048,
            (float*)p_dpart, EMBD, (size_t)BB * EMBD, 2048 / OSPLIT);
        reduce_dec<<<(BB * EMBD) / 256, 256>>>();
        // vocab logits straight into d_out[b, t, :]  (250 blocks)
        sgemm128<<<dim3(VV / 128, 1, 1), 256>>>(
            (const float*)p_dec, EMBD, W_vocab, EMBD,
            out + (size_t)t * VV, (size_t)TT * VV, 0, EMBD);
        argmax_embed<<<BB, 1024>>>(out, emb, t);
    }

    // final log-softmax in place over all B*T rows
    logsoftmax_rows<<<BB * TT, 1024>>>(out);

    // tgt_len output: always T (== 50) per the reference's final where()
    long extra = (long)out_size - (long)BB * TT * VV;
    if (extra > 0)
        fill_tail<<<(unsigned)((extra + 255) / 256), 256>>>(
            out + (size_t)BB * TT * VV, extra, 50.0f);
}

// round 9
// speedup vs baseline: 2.8086x; 1.0017x over previous
#include <cuda_runtime.h>
#include <math.h>

// Problem constants (fixed by the reference)
#define BB   64
#define SS   128
#define HH   1024
#define EE   1024
#define EMBD 512
#define VV   32000
#define TT   50
#define KCAT 1536          // EMBD + HH
#define NGATE 4096         // 4*HH
#define GSPLIT 8           // split-K for gates GEMM (KCAT/8 = 192)
#define OSPLIT 32          // split-K for out-projection GEMM (2048/32 = 64)

// ---------------------------------------------------------------------------
// Device scratch (static device globals — no allocation)
// ---------------------------------------------------------------------------
__device__ float g_keys[(size_t)BB * SS * HH];       // att keys [B,S,H]
__device__ float g_wcat[(size_t)NGATE * KCAT];       // [W_ih | W_hh]
__device__ float g_xcat[BB * KCAT];                  // [prev_emb | h]
__device__ float g_hc[BB * 2048];                    // [h | c_t]
__device__ float g_c[BB * HH];                       // LSTM cell state
__device__ float g_gpart[GSPLIT * BB * NGATE];       // gates partials
__device__ float g_dpart[OSPLIT * BB * EMBD];        // out-proj partials
__device__ float g_dec[BB * EMBD];                   // out-projection result
__device__ float g_scores[BB * SS];                  // attention scores

// ---------------------------------------------------------------------------
// High-throughput SGEMM:  C[M,N] = A[M,K]*B[N,K]^T
// Block tile 64x128, TK=32, 256 threads, 8x4 micro-tile.
//   - A smem reads: warp-uniform (broadcast, conflict-free)
//   - B smem reads: lane*16B contiguous (conflict-free LDS.128)
// blockIdx.x -> N tile, blockIdx.y -> M tile, blockIdx.z -> split-K slice.
// Requires: kLen % 32 == 0, M mult of 64, N mult of 128, lda/ldb mult of 4.
// ---------------------------------------------------------------------------
__global__ void __launch_bounds__(256)
sgemm128(const float* __restrict__ A, int lda,
         const float* __restrict__ B, int ldb,
         float* __restrict__ C, size_t ldc, size_t splitStride, int kLen)
{
    constexpr int TM = 64, TN = 128, TK = 32;
    __shared__ float As[2][TK][TM + 4];
    __shared__ float Bs[2][TK][TN + 4];

    const int tid = threadIdx.x;
    const int m0  = blockIdx.y * TM;
    const int n0  = blockIdx.x * TN;

    A += (size_t)m0 * lda + (size_t)blockIdx.z * kLen;
    B += (size_t)n0 * ldb + (size_t)blockIdx.z * kLen;
    C += (size_t)blockIdx.z * splitStride + (size_t)m0 * ldc + n0;

    // loaders
    const int ar = tid >> 2;            // A row 0..63
    const int ak = (tid & 3) * 4;       // A k base {0,4,8,12} (+16)
    const int br = tid >> 1;            // B row 0..127
    const int bk = (tid & 1) * 4;       // B k base {0,4} (+8,+16,+24)
    const float* Ald = A + (size_t)ar * lda + ak;
    const float* Bld = B + (size_t)br * ldb + bk;

    float4 ra0 = *(const float4*)(Ald);
    float4 ra1 = *(const float4*)(Ald + 16);
    float4 rb0 = *(const float4*)(Bld);
    float4 rb1 = *(const float4*)(Bld + 8);
    float4 rb2 = *(const float4*)(Bld + 16);
    float4 rb3 = *(const float4*)(Bld + 24);

    // compute mapping: 8 rows x 4 cols per thread
    const int rg = tid >> 5;            // warp id 0..7  -> rows rg*8..rg*8+7
    const int cg = tid & 31;            // lane          -> cols cg*4..cg*4+3

    float acc[8][4];
#pragma unroll
    for (int i = 0; i < 8; i++)
#pragma unroll
        for (int j = 0; j < 4; j++) acc[i][j] = 0.f;

    const int nk = kLen / TK;
    int buf = 0;

#define STORE_TILE128(bf)                                                     \
    {   As[bf][ak+ 0][ar]=ra0.x; As[bf][ak+ 1][ar]=ra0.y;                     \
        As[bf][ak+ 2][ar]=ra0.z; As[bf][ak+ 3][ar]=ra0.w;                     \
        As[bf][ak+16][ar]=ra1.x; As[bf][ak+17][ar]=ra1.y;                     \
        As[bf][ak+18][ar]=ra1.z; As[bf][ak+19][ar]=ra1.w;                     \
        Bs[bf][bk+ 0][br]=rb0.x; Bs[bf][bk+ 1][br]=rb0.y;                     \
        Bs[bf][bk+ 2][br]=rb0.z; Bs[bf][bk+ 3][br]=rb0.w;                     \
        Bs[bf][bk+ 8][br]=rb1.x; Bs[bf][bk+ 9][br]=rb1.y;                     \
        Bs[bf][bk+10][br]=rb1.z; Bs[bf][bk+11][br]=rb1.w;                     \
        Bs[bf][bk+16][br]=rb2.x; Bs[bf][bk+17][br]=rb2.y;                     \
        Bs[bf][bk+18][br]=rb2.z; Bs[bf][bk+19][br]=rb2.w;                     \
        Bs[bf][bk+24][br]=rb3.x; Bs[bf][bk+25][br]=rb3.y;                     \
        Bs[bf][bk+26][br]=rb3.z; Bs[bf][bk+27][br]=rb3.w; }

    STORE_TILE128(0);
    __syncthreads();

    for (int kt = 0; kt < nk; kt++) {
        if (kt + 1 < nk) {                      // prefetch next tile to regs
            const float* Ap = Ald + (kt + 1) * TK;
            const float* Bp = Bld + (kt + 1) * TK;
            ra0 = *(const float4*)(Ap);
            ra1 = *(const float4*)(Ap + 16);
            rb0 = *(const float4*)(Bp);
            rb1 = *(const float4*)(Bp + 8);
            rb2 = *(const float4*)(Bp + 16);
            rb3 = *(const float4*)(Bp + 24);
        }
#pragma unroll
        for (int k = 0; k < TK; k++) {
            float4 a0 = *(const float4*)&As[buf][k][rg * 8];      // broadcast
            float4 a1 = *(const float4*)&As[buf][k][rg * 8 + 4];  // broadcast
            float4 b  = *(const float4*)&Bs[buf][k][cg * 4];      // conflict-free
            acc[0][0]=fmaf(a0.x,b.x,acc[0][0]); acc[0][1]=fmaf(a0.x,b.y,acc[0][1]);
            acc[0][2]=fmaf(a0.x,b.z,acc[0][2]); acc[0][3]=fmaf(a0.x,b.w,acc[0][3]);
            acc[1][0]=fmaf(a0.y,b.x,acc[1][0]); acc[1][1]=fmaf(a0.y,b.y,acc[1][1]);
            acc[1][2]=fmaf(a0.y,b.z,acc[1][2]); acc[1][3]=fmaf(a0.y,b.w,acc[1][3]);
            acc[2][0]=fmaf(a0.z,b.x,acc[2][0]); acc[2][1]=fmaf(a0.z,b.y,acc[2][1]);
            acc[2][2]=fmaf(a0.z,b.z,acc[2][2]); acc[2][3]=fmaf(a0.z,b.w,acc[2][3]);
            acc[3][0]=fmaf(a0.w,b.x,acc[3][0]); acc[3][1]=fmaf(a0.w,b.y,acc[3][1]);
            acc[3][2]=fmaf(a0.w,b.z,acc[3][2]); acc[3][3]=fmaf(a0.w,b.w,acc[3][3]);
            acc[4][0]=fmaf(a1.x,b.x,acc[4][0]); acc[4][1]=fmaf(a1.x,b.y,acc[4][1]);
            acc[4][2]=fmaf(a1.x,b.z,acc[4][2]); acc[4][3]=fmaf(a1.x,b.w,acc[4][3]);
            acc[5][0]=fmaf(a1.y,b.x,acc[5][0]); acc[5][1]=fmaf(a1.y,b.y,acc[5][1]);
            acc[5][2]=fmaf(a1.y,b.z,acc[5][2]); acc[5][3]=fmaf(a1.y,b.w,acc[5][3]);
            acc[6][0]=fmaf(a1.z,b.x,acc[6][0]); acc[6][1]=fmaf(a1.z,b.y,acc[6][1]);
            acc[6][2]=fmaf(a1.z,b.z,acc[6][2]); acc[6][3]=fmaf(a1.z,b.w,acc[6][3]);
            acc[7][0]=fmaf(a1.w,b.x,acc[7][0]); acc[7][1]=fmaf(a1.w,b.y,acc[7][1]);
            acc[7][2]=fmaf(a1.w,b.z,acc[7][2]); acc[7][3]=fmaf(a1.w,b.w,acc[7][3]);
        }
        if (kt + 1 < nk) {
            __syncthreads();
            STORE_TILE128(buf ^ 1);
            __syncthreads();
            buf ^= 1;
        }
    }
#undef STORE_TILE128

#pragma unroll
    for (int i = 0; i < 8; i++) {
        float4 o = make_float4(acc[i][0], acc[i][1], acc[i][2], acc[i][3]);
        *(float4*)(C + (size_t)(rg * 8 + i) * ldc + cg * 4) = o;   // coalesced
    }
}

// ---------------------------------------------------------------------------
// Small SGEMM (TN=64, 4x4 micro-tile) — used only for the tiny out-projection
// ---------------------------------------------------------------------------
__global__ void __launch_bounds__(256)
sgemm64(const float* __restrict__ A, int lda,
        const float* __restrict__ B, int ldb,
        float* __restrict__ C, size_t ldc, size_t splitStride, int kLen)
{
    constexpr int TM = 64, TN = 64, TK = 32;
    __shared__ float As[2][TK][TM + 4];
    __shared__ float Bs[2][TK][TN + 4];

    const int tid = threadIdx.x;
    const int m0  = blockIdx.y * TM;
    const int n0  = blockIdx.x * TN;

    A += (size_t)m0 * lda + (size_t)blockIdx.z * kLen;
    B += (size_t)n0 * ldb + (size_t)blockIdx.z * kLen;
    C += (size_t)blockIdx.z * splitStride + (size_t)m0 * ldc + n0;

    const int lr  = tid >> 2;
    const int lc4 = tid & 3;
    const int tx  = tid & 15;
    const int ty  = tid >> 4;

    const float* Ald = A + (size_t)lr * lda + lc4 * 4;
    const float* Bld = B + (size_t)lr * ldb + lc4 * 4;

    float4 ra0 = *(const float4*)(Ald);
    float4 ra1 = *(const float4*)(Ald + 16);
    float4 rb0 = *(const float4*)(Bld);
    float4 rb1 = *(const float4*)(Bld + 16);

    float acc[4][4];
#pragma unroll
    for (int i = 0; i < 4; i++)
#pragma unroll
        for (int j = 0; j < 4; j++) acc[i][j] = 0.f;

    const int nk = kLen / TK;
    int buf = 0;

#define STORE_TILE(bf)                                                        \
    {   int kk0 = lc4 * 4;                                                    \
        As[bf][kk0+ 0][lr]=ra0.x; As[bf][kk0+ 1][lr]=ra0.y;                   \
        As[bf][kk0+ 2][lr]=ra0.z; As[bf][kk0+ 3][lr]=ra0.w;                   \
        As[bf][kk0+16][lr]=ra1.x; As[bf][kk0+17][lr]=ra1.y;                   \
        As[bf][kk0+18][lr]=ra1.z; As[bf][kk0+19][lr]=ra1.w;                   \
        Bs[bf][kk0+ 0][lr]=rb0.x; Bs[bf][kk0+ 1][lr]=rb0.y;                   \
        Bs[bf][kk0+ 2][lr]=rb0.z; Bs[bf][kk0+ 3][lr]=rb0.w;                   \
        Bs[bf][kk0+16][lr]=rb1.x; Bs[bf][kk0+17][lr]=rb1.y;                   \
        Bs[bf][kk0+18][lr]=rb1.z; Bs[bf][kk0+19][lr]=rb1.w; }

    STORE_TILE(0);
    __syncthreads();

    for (int kt = 0; kt < nk; kt++) {
        if (kt + 1 < nk) {
            const float* Ap = Ald + (kt + 1) * TK;
            const float* Bp = Bld + (kt + 1) * TK;
            ra0 = *(const float4*)(Ap);
            ra1 = *(const float4*)(Ap + 16);
            rb0 = *(const float4*)(Bp);
            rb1 = *(const float4*)(Bp + 16);
        }
#pragma unroll
        for (int k = 0; k < TK; k++) {
            float4 a = *(const float4*)&As[buf][k][ty * 4];
            float4 b = *(const float4*)&Bs[buf][k][tx * 4];
            acc[0][0]=fmaf(a.x,b.x,acc[0][0]); acc[0][1]=fmaf(a.x,b.y,acc[0][1]);
            acc[0][2]=fmaf(a.x,b.z,acc[0][2]); acc[0][3]=fmaf(a.x,b.w,acc[0][3]);
            acc[1][0]=fmaf(a.y,b.x,acc[1][0]); acc[1][1]=fmaf(a.y,b.y,acc[1][1]);
            acc[1][2]=fmaf(a.y,b.z,acc[1][2]); acc[1][3]=fmaf(a.y,b.w,acc[1][3]);
            acc[2][0]=fmaf(a.z,b.x,acc[2][0]); acc[2][1]=fmaf(a.z,b.y,acc[2][1]);
            acc[2][2]=fmaf(a.z,b.z,acc[2][2]); acc[2][3]=fmaf(a.z,b.w,acc[2][3]);
            acc[3][0]=fmaf(a.w,b.x,acc[3][0]); acc[3][1]=fmaf(a.w,b.y,acc[3][1]);
            acc[3][2]=fmaf(a.w,b.z,acc[3][2]); acc[3][3]=fmaf(a.w,b.w,acc[3][3]);
        }
        if (kt + 1 < nk) {
            __syncthreads();
            STORE_TILE(buf ^ 1);
            __syncthreads();
            buf ^= 1;
        }
    }
#undef STORE_TILE

#pragma unroll
    for (int i = 0; i < 4; i++) {
        float4 o = make_float4(acc[i][0], acc[i][1], acc[i][2], acc[i][3]);
        *(float4*)(C + (size_t)(ty * 4 + i) * ldc + tx * 4) = o;
    }
}

// ---------------------------------------------------------------------------
// Setup kernels
// ---------------------------------------------------------------------------
__global__ void build_wcat(const float* __restrict__ W_ih,
                           const float* __restrict__ W_hh)
{
    size_t total = (size_t)NGATE * KCAT;
    for (size_t i = (size_t)blockIdx.x * blockDim.x + threadIdx.x; i < total;
         i += (size_t)gridDim.x * blockDim.x) {
        int j = (int)(i / KCAT);
        int k = (int)(i % KCAT);
        g_wcat[i] = (k < EMBD) ? W_ih[(size_t)j * EMBD + k]
                               : W_hh[(size_t)j * HH + (k - EMBD)];
    }
}

__global__ void init_state(const float* __restrict__ dec_init)
{
    int idx = blockIdx.x * blockDim.x + threadIdx.x;   // B*H
    int b = idx >> 10, j = idx & 1023;
    float h0 = dec_init[idx];
    g_hc[b * 2048 + j] = h0;
    g_xcat[b * KCAT + EMBD + j] = h0;
    g_c[idx] = dec_init[BB * HH + idx];
    if (j < EMBD) g_xcat[b * KCAT + j] = 0.f;
}

// ---------------------------------------------------------------------------
// LSTM cell: sum GSPLIT gate partials + bias, apply nonlinearity
// ---------------------------------------------------------------------------
__device__ __forceinline__ float sigf(float x) { return 1.f / (1.f + expf(-x)); }

__global__ void lstm_cell(const float* __restrict__ b_lstm)
{
    int idx = blockIdx.x * blockDim.x + threadIdx.x;   // B*H
    int b = idx >> 10, j = idx & 1023;
    const float* gp = g_gpart + (size_t)b * NGATE;
    const size_t SP = (size_t)BB * NGATE;
    float ig = b_lstm[j], fg = b_lstm[1024 + j],
          gg = b_lstm[2048 + j], og = b_lstm[3072 + j];
#pragma unroll
    for (int s = 0; s < GSPLIT; s++) {
        ig += gp[s * SP + j];
        fg += gp[s * SP + 1024 + j];
        gg += gp[s * SP + 2048 + j];
        og += gp[s * SP + 3072 + j];
    }
    float c = sigf(fg) * g_c[idx] + sigf(ig) * tanhf(gg);
    float h = sigf(og) * tanhf(c);
    g_c[idx] = c;
    g_hc[b * 2048 + j] = h;
    g_xcat[b * KCAT + EMBD + j] = h;
}

// ---------------------------------------------------------------------------
// Attention scores: grid (4, B); each block does 32 rows of keys . h
// ---------------------------------------------------------------------------
__global__ void __launch_bounds__(256)
attn_scores()
{
    int b = blockIdx.y;
    int tid = threadIdx.x, warp = tid >> 5, lane = tid & 31;
    __shared__ float4 sh4[HH / 4];

    const float4* h4 = (const float4*)&g_hc[b * 2048];
    sh4[tid] = h4[tid];
    __syncthreads();

#pragma unroll
    for (int r = 0; r < 4; r++) {
        int s = blockIdx.x * 32 + warp * 4 + r;
        const float4* k4 = (const float4*)&g_keys[((size_t)b * SS + s) * HH];
        float acc = 0.f;
#pragma unroll
        for (int i = 0; i < 8; i++) {
            float4 kv = k4[lane + 32 * i];
            float4 hv = sh4[lane + 32 * i];
            acc = fmaf(kv.x, hv.x, acc);
            acc = fmaf(kv.y, hv.y, acc);
            acc = fmaf(kv.z, hv.z, acc);
            acc = fmaf(kv.w, hv.w, acc);
        }
#pragma unroll
        for (int o = 16; o; o >>= 1) acc += __shfl_xor_sync(0xffffffffu, acc, o);
        if (lane == 0) g_scores[b * SS + s] = acc;
    }
}

// ---------------------------------------------------------------------------
// Attention context (softmax fused, recomputed per block): grid (4, B)
// ---------------------------------------------------------------------------
__global__ void __launch_bounds__(256)
attn_context(const float* __restrict__ enc, const int* __restrict__ enc_len)
{
    int b = blockIdx.y, e0 = blockIdx.x * 256;
    int tid = threadIdx.x, warp = tid >> 5, lane = tid & 31;
    __shared__ float sa[SS];
    __shared__ float red[8];
    __shared__ float bc;

    int len = enc_len[b];
    float v = -1e9f;
    if (tid < SS) {
        float s = g_scores[b * SS + tid];
        v = (tid < len) ? s : -1e9f;
        sa[tid] = v;
    }
    float m = v;
#pragma unroll
    for (int o = 16; o; o >>= 1) m = fmaxf(m, __shfl_xor_sync(0xffffffffu, m, o));
    if (lane == 0) red[warp] = m;
    __syncthreads();
    if (tid == 0) {
        float mm = red[0];
        for (int i = 1; i < 4; i++) mm = fmaxf(mm, red[i]);
        bc = mm;
    }
    __syncthreads();
    float mx = bc;

    float e = (tid < SS) ? expf(v - mx) : 0.f;
    float s2 = e;
#pragma unroll
    for (int o = 16; o; o >>= 1) s2 += __shfl_xor_sync(0xffffffffu, s2, o);
    __syncthreads();
    if (lane == 0) red[warp] = s2;
    __syncthreads();
    if (tid == 0) bc = red[0] + red[1] + red[2] + red[3];
    __syncthreads();
    float inv = 1.f / bc;
    if (tid < SS) sa[tid] = e * inv;
    __syncthreads();

    const float* ep = enc + ((size_t)b * SS) * EE + e0 + tid;
    float acc = 0.f;
    int s = 0;
    for (; s + 4 <= len; s += 4) {
        float x0 = ep[(size_t)(s + 0) * EE];
        float x1 = ep[(size_t)(s + 1) * EE];
        float x2 = ep[(size_t)(s + 2) * EE];
        float x3 = ep[(size_t)(s + 3) * EE];
        acc = fmaf(sa[s + 0], x0, acc);
        acc = fmaf(sa[s + 1], x1, acc);
        acc = fmaf(sa[s + 2], x2, acc);
        acc = fmaf(sa[s + 3], x3, acc);
    }
    for (; s < len; s++) acc = fmaf(sa[s], ep[(size_t)s * EE], acc);
    g_hc[b * 2048 + HH + e0 + tid] = acc;
}

// ---------------------------------------------------------------------------
// Reduce out-projection split-K partials
// ---------------------------------------------------------------------------
__global__ void reduce_dec()
{
    int idx = blockIdx.x * blockDim.x + threadIdx.x;   // B*EMBD
    float a = 0.f;
#pragma unroll
    for (int s = 0; s < OSPLIT; s++) a += g_dpart[(size_t)s * BB * EMBD + idx];
    g_dec[idx] = a;
}

// ---------------------------------------------------------------------------
// Greedy argmax over logits row + embedding gather
// ---------------------------------------------------------------------------
__global__ void __launch_bounds__(1024)
argmax_embed(const float* __restrict__ logits, const float* __restrict__ emb, int t)
{
    int b = blockIdx.x;
    const float4* row4 = (const float4*)(logits + ((size_t)b * TT + t) * VV);
    int tid = threadIdx.x;

    float bv = -INFINITY;
    int   bi = 0x7fffffff;
#pragma unroll
    for (int j = 0; j < 8; j++) {
        int v4 = j * 1024 + tid;
        if (v4 < VV / 4) {
            float4 x = row4[v4];
            int base = v4 * 4;
            if (x.x > bv || (x.x == bv && base     < bi)) { bv = x.x; bi = base;     }
            if (x.y > bv || (x.y == bv && base + 1 < bi)) { bv = x.y; bi = base + 1; }
            if (x.z > bv || (x.z == bv && base + 2 < bi)) { bv = x.z; bi = base + 2; }
            if (x.w > bv || (x.w == bv && base + 3 < bi)) { bv = x.w; bi = base + 3; }
        }
    }
#pragma unroll
    for (int o = 16; o; o >>= 1) {
        float ov = __shfl_xor_sync(0xffffffffu, bv, o);
        int   oi = __shfl_xor_sync(0xffffffffu, bi, o);
        if (ov > bv || (ov == bv && oi < bi)) { bv = ov; bi = oi; }
    }
    __shared__ float sv[32];
    __shared__ int   si[32];
    __shared__ int   ssym;
    int warp = tid >> 5, lane = tid & 31;
    if (lane == 0) { sv[warp] = bv; si[warp] = bi; }
    __syncthreads();
    if (warp == 0) {
        bv = sv[lane]; bi = si[lane];
#pragma unroll
        for (int o = 16; o; o >>= 1) {
            float ov = __shfl_xor_sync(0xffffffffu, bv, o);
            int   oi = __shfl_xor_sync(0xffffffffu, bi, o);
            if (ov > bv || (ov == bv && oi < bi)) { bv = ov; bi = oi; }
        }
        if (lane == 0) ssym = bi;
    }
    __syncthreads();
    int sym = ssym;
    if (tid < EMBD / 4) {
        const float4* er = (const float4*)(emb + (size_t)sym * EMBD);
        ((float4*)&g_xcat[b * KCAT])[tid] = er[tid];
    }
}

// ---------------------------------------------------------------------------
// Fused in-place log-softmax over each [VV] row of d_out
// ---------------------------------------------------------------------------
__global__ void __launch_bounds__(1024)
logsoftmax_rows(float* __restrict__ out)
{
    float* p = out + (size_t)blockIdx.x * VV;
    int tid = threadIdx.x;

    float x[32];
    float mx = -INFINITY;
#pragma unroll
    for (int i = 0; i < 32; i++) {
        int v = tid + (i << 10);
        x[i] = (v < VV) ? p[v] : -INFINITY;
        mx = fmaxf(mx, x[i]);
    }
    __shared__ float red[32];
    __shared__ float bc;
#pragma unroll
    for (int o = 16; o; o >>= 1) mx = fmaxf(mx, __shfl_xor_sync(0xffffffffu, mx, o));
    if ((tid & 31) == 0) red[tid >> 5] = mx;
    __syncthreads();
    if (tid < 32) {
        float m = red[tid];
#pragma unroll
        for (int o = 16; o; o >>= 1) m = fmaxf(m, __shfl_xor_sync(0xffffffffu, m, o));
        if (tid == 0) bc = m;
    }
    __syncthreads();
    float M = bc;

    float s = 0.f;
#pragma unroll
    for (int i = 0; i < 32; i++) s += expf(x[i] - M);
    __syncthreads();
#pragma unroll
    for (int o = 16; o; o >>= 1) s += __shfl_xor_sync(0xffffffffu, s, o);
    if ((tid & 31) == 0) red[tid >> 5] = s;
    __syncthreads();
    if (tid < 32) {
        float m = red[tid];
#pragma unroll
        for (int o = 16; o; o >>= 1) m += __shfl_xor_sync(0xffffffffu, m, o);
        if (tid == 0) bc = m;
    }
    __syncthreads();
    float lz = M + logf(bc);
#pragma unroll
    for (int i = 0; i < 32; i++) {
        int v = tid + (i << 10);
        if (v < VV) p[v] = x[i] - lz;
    }
}

__global__ void fill_tail(float* __restrict__ p, long n, float val)
{
    long i = (long)blockIdx.x * blockDim.x + threadIdx.x;
    if (i < n) p[i] = val;
}

// ---------------------------------------------------------------------------
// Launch
// ---------------------------------------------------------------------------
extern "C" void kernel_launch(void* const* d_in, const int* in_sizes, int n_in,
                              void* d_out, int out_size)
{
    const float* dec_init  = (const float*)d_in[0];
    const float* enc       = (const float*)d_in[1];
    const int*   enc_len   = (const int*)d_in[2];
    /* d_in[3] = tgt (unused in eval mode) */
    const float* W_ih      = (const float*)d_in[4];
    const float* W_hh      = (const float*)d_in[5];
    const float* b_lstm    = (const float*)d_in[6];
    const float* W_attproj = (const float*)d_in[7];
    const float* W_out     = (const float*)d_in[8];
    const float* W_vocab   = (const float*)d_in[9];
    const float* emb       = (const float*)d_in[10];
    float* out = (float*)d_out;

    void *p_keys, *p_wcat, *p_xcat, *p_hc, *p_gpart, *p_dpart, *p_dec;
    cudaGetSymbolAddress(&p_keys,  g_keys);
    cudaGetSymbolAddress(&p_wcat,  g_wcat);
    cudaGetSymbolAddress(&p_xcat,  g_xcat);
    cudaGetSymbolAddress(&p_hc,    g_hc);
    cudaGetSymbolAddress(&p_gpart, g_gpart);
    cudaGetSymbolAddress(&p_dpart, g_dpart);
    cudaGetSymbolAddress(&p_dec,   g_dec);

    // one-time setup
    build_wcat<<<2048, 256>>>(W_ih, W_hh);
    init_state<<<(BB * HH) / 256, 256>>>(dec_init);
    // keys[B*S, H] = enc[B*S, E] @ W_attproj^T   (grid 8 x 128 = 1024 blocks)
    sgemm128<<<dim3(HH / 128, (BB * SS) / 64, 1), 256>>>(
        enc, EE, W_attproj, EE, (float*)p_keys, HH, 0, EE);

    for (int t = 0; t < TT; t++) {
        // gates partials: split-K x8  (32 x 8 = 256 blocks, kLen=192)
        sgemm128<<<dim3(NGATE / 128, 1, GSPLIT), 256>>>(
            (const float*)p_xcat, KCAT, (const float*)p_wcat, KCAT,
            (float*)p_gpart, NGATE, (size_t)BB * NGATE, KCAT / GSPLIT);
        lstm_cell<<<(BB * HH) / 256, 256>>>(b_lstm);
        attn_scores<<<dim3(4, BB), 256>>>();
        attn_context<<<dim3(4, BB), 256>>>(enc, enc_len);
        // dec partials: split-K x32  (8 x 32 = 256 blocks, kLen=64)
        sgemm64<<<dim3(EMBD / 64, 1, OSPLIT), 256>>>(
            (const float*)p_hc, 2048, W_out, 2048,
            (float*)p_dpart, EMBD, (size_t)BB * EMBD, 2048 / OSPLIT);
        reduce_dec<<<(BB * EMBD) / 256, 256>>>();
        // vocab logits straight into d_out[b, t, :]  (250 blocks)
        sgemm128<<<dim3(VV / 128, 1, 1), 256>>>(
            (const float*)p_dec, EMBD, W_vocab, EMBD,
            out + (size_t)t * VV, (size_t)TT * VV, 0, EMBD);
        argmax_embed<<<BB, 1024>>>(out, emb, t);
    }

    // final log-softmax in place over all B*T rows
    logsoftmax_rows<<<BB * TT, 1024>>>(out);

    // tgt_len output: always T (== 50) per the reference's final where()
    long extra = (long)out_size - (long)BB * TT * VV;
    if (extra > 0)
        fill_tail<<<(unsigned)((extra + 255) / 256), 256>>>(
            out + (size_t)BB * TT * VV, extra, 50.0f);
}

// round 10
// speedup vs baseline: 2.8339x; 1.0090x over previous
#include <cuda_runtime.h>
#include <math.h>

// Problem constants (fixed by the reference)
#define BB   64
#define SS   128
#define HH   1024
#define EE   1024
#define EMBD 512
#define VV   32000
#define TT   50
#define KCAT 1536          // EMBD + HH
#define NGATE 4096         // 4*HH
#define GSPLIT 8           // split-K for gates GEMM (KCAT/8 = 192)
#define OSPLIT 32          // split-K for out-projection GEMM (2048/32 = 64)

// ---------------------------------------------------------------------------
// Device scratch (static device globals — no allocation)
// ---------------------------------------------------------------------------
__device__ float g_keys[(size_t)BB * SS * HH];       // att keys [B,S,H]
__device__ float g_wcat[(size_t)NGATE * KCAT];       // [W_ih | W_hh]
__device__ float g_xcat[BB * KCAT];                  // [prev_emb | h]
__device__ float g_hc[BB * 2048];                    // [h | c_t]
__device__ float g_c[BB * HH];                       // LSTM cell state
__device__ float g_gpart[GSPLIT * BB * NGATE];       // gates partials
__device__ float g_dpart[OSPLIT * BB * EMBD];        // out-proj partials
__device__ float g_dec[BB * EMBD];                   // out-projection result
__device__ float g_scores[BB * SS];                  // attention scores

// ---------------------------------------------------------------------------
// High-throughput SGEMM:  C[M,N] = A[M,K]*B[N,K]^T
// Block tile 64x128, TK=32, 256 threads, 8x4 micro-tile.
// Single __syncthreads per k-tile: prefetch(regs) -> compute(buf) ->
// store(buf^1) -> sync. Store targets the opposite buffer and no warp can be
// more than one iteration ahead, so the pre-store barrier is unnecessary.
// ---------------------------------------------------------------------------
__global__ void __launch_bounds__(256)
sgemm128(const float* __restrict__ A, int lda,
         const float* __restrict__ B, int ldb,
         float* __restrict__ C, size_t ldc, size_t splitStride, int kLen)
{
    constexpr int TM = 64, TN = 128, TK = 32;
    __shared__ float As[2][TK][TM + 4];
    __shared__ float Bs[2][TK][TN + 4];

    const int tid = threadIdx.x;
    const int m0  = blockIdx.y * TM;
    const int n0  = blockIdx.x * TN;

    A += (size_t)m0 * lda + (size_t)blockIdx.z * kLen;
    B += (size_t)n0 * ldb + (size_t)blockIdx.z * kLen;
    C += (size_t)blockIdx.z * splitStride + (size_t)m0 * ldc + n0;

    // loaders
    const int ar = tid >> 2;            // A row 0..63
    const int ak = (tid & 3) * 4;       // A k base {0,4,8,12} (+16)
    const int br = tid >> 1;            // B row 0..127
    const int bk = (tid & 1) * 4;       // B k base {0,4} (+8,+16,+24)
    const float* Ald = A + (size_t)ar * lda + ak;
    const float* Bld = B + (size_t)br * ldb + bk;

    float4 ra0 = *(const float4*)(Ald);
    float4 ra1 = *(const float4*)(Ald + 16);
    float4 rb0 = *(const float4*)(Bld);
    float4 rb1 = *(const float4*)(Bld + 8);
    float4 rb2 = *(const float4*)(Bld + 16);
    float4 rb3 = *(const float4*)(Bld + 24);

    // compute mapping: 8 rows x 4 cols per thread
    const int rg = tid >> 5;            // warp id 0..7  -> rows rg*8..rg*8+7
    const int cg = tid & 31;            // lane          -> cols cg*4..cg*4+3

    float acc[8][4];
#pragma unroll
    for (int i = 0; i < 8; i++)
#pragma unroll
        for (int j = 0; j < 4; j++) acc[i][j] = 0.f;

    const int nk = kLen / TK;
    int buf = 0;

#define STORE_TILE128(bf)                                                     \
    {   As[bf][ak+ 0][ar]=ra0.x; As[bf][ak+ 1][ar]=ra0.y;                     \
        As[bf][ak+ 2][ar]=ra0.z; As[bf][ak+ 3][ar]=ra0.w;                     \
        As[bf][ak+16][ar]=ra1.x; As[bf][ak+17][ar]=ra1.y;                     \
        As[bf][ak+18][ar]=ra1.z; As[bf][ak+19][ar]=ra1.w;                     \
        Bs[bf][bk+ 0][br]=rb0.x; Bs[bf][bk+ 1][br]=rb0.y;                     \
        Bs[bf][bk+ 2][br]=rb0.z; Bs[bf][bk+ 3][br]=rb0.w;                     \
        Bs[bf][bk+ 8][br]=rb1.x; Bs[bf][bk+ 9][br]=rb1.y;                     \
        Bs[bf][bk+10][br]=rb1.z; Bs[bf][bk+11][br]=rb1.w;                     \
        Bs[bf][bk+16][br]=rb2.x; Bs[bf][bk+17][br]=rb2.y;                     \
        Bs[bf][bk+18][br]=rb2.z; Bs[bf][bk+19][br]=rb2.w;                     \
        Bs[bf][bk+24][br]=rb3.x; Bs[bf][bk+25][br]=rb3.y;                     \
        Bs[bf][bk+26][br]=rb3.z; Bs[bf][bk+27][br]=rb3.w; }

    STORE_TILE128(0);
    __syncthreads();

    for (int kt = 0; kt < nk; kt++) {
        if (kt + 1 < nk) {                      // prefetch next tile to regs
            const float* Ap = Ald + (kt + 1) * TK;
            const float* Bp = Bld + (kt + 1) * TK;
            ra0 = *(const float4*)(Ap);
            ra1 = *(const float4*)(Ap + 16);
            rb0 = *(const float4*)(Bp);
            rb1 = *(const float4*)(Bp + 8);
            rb2 = *(const float4*)(Bp + 16);
            rb3 = *(const float4*)(Bp + 24);
        }
#pragma unroll
        for (int k = 0; k < TK; k++) {
            float4 a0 = *(const float4*)&As[buf][k][rg * 8];      // broadcast
            float4 a1 = *(const float4*)&As[buf][k][rg * 8 + 4];  // broadcast
            float4 b  = *(const float4*)&Bs[buf][k][cg * 4];      // conflict-free
            acc[0][0]=fmaf(a0.x,b.x,acc[0][0]); acc[0][1]=fmaf(a0.x,b.y,acc[0][1]);
            acc[0][2]=fmaf(a0.x,b.z,acc[0][2]); acc[0][3]=fmaf(a0.x,b.w,acc[0][3]);
            acc[1][0]=fmaf(a0.y,b.x,acc[1][0]); acc[1][1]=fmaf(a0.y,b.y,acc[1][1]);
            acc[1][2]=fmaf(a0.y,b.z,acc[1][2]); acc[1][3]=fmaf(a0.y,b.w,acc[1][3]);
            acc[2][0]=fmaf(a0.z,b.x,acc[2][0]); acc[2][1]=fmaf(a0.z,b.y,acc[2][1]);
            acc[2][2]=fmaf(a0.z,b.z,acc[2][2]); acc[2][3]=fmaf(a0.z,b.w,acc[2][3]);
            acc[3][0]=fmaf(a0.w,b.x,acc[3][0]); acc[3][1]=fmaf(a0.w,b.y,acc[3][1]);
            acc[3][2]=fmaf(a0.w,b.z,acc[3][2]); acc[3][3]=fmaf(a0.w,b.w,acc[3][3]);
            acc[4][0]=fmaf(a1.x,b.x,acc[4][0]); acc[4][1]=fmaf(a1.x,b.y,acc[4][1]);
            acc[4][2]=fmaf(a1.x,b.z,acc[4][2]); acc[4][3]=fmaf(a1.x,b.w,acc[4][3]);
            acc[5][0]=fmaf(a1.y,b.x,acc[5][0]); acc[5][1]=fmaf(a1.y,b.y,acc[5][1]);
            acc[5][2]=fmaf(a1.y,b.z,acc[5][2]); acc[5][3]=fmaf(a1.y,b.w,acc[5][3]);
            acc[6][0]=fmaf(a1.z,b.x,acc[6][0]); acc[6][1]=fmaf(a1.z,b.y,acc[6][1]);
            acc[6][2]=fmaf(a1.z,b.z,acc[6][2]); acc[6][3]=fmaf(a1.z,b.w,acc[6][3]);
            acc[7][0]=fmaf(a1.w,b.x,acc[7][0]); acc[7][1]=fmaf(a1.w,b.y,acc[7][1]);
            acc[7][2]=fmaf(a1.w,b.z,acc[7][2]); acc[7][3]=fmaf(a1.w,b.w,acc[7][3]);
        }
        if (kt + 1 < nk) {
            STORE_TILE128(buf ^ 1);    // opposite buffer: safe without pre-sync
            __syncthreads();
            buf ^= 1;
        }
    }
#undef STORE_TILE128

#pragma unroll
    for (int i = 0; i < 8; i++) {
        float4 o = make_float4(acc[i][0], acc[i][1], acc[i][2], acc[i][3]);
        *(float4*)(C + (size_t)(rg * 8 + i) * ldc + cg * 4) = o;   // coalesced
    }
}

// ---------------------------------------------------------------------------
// Small SGEMM (TN=64, 4x4 micro-tile) — only the tiny out-projection
// ---------------------------------------------------------------------------
__global__ void __launch_bounds__(256)
sgemm64(const float* __restrict__ A, int lda,
        const float* __restrict__ B, int ldb,
        float* __restrict__ C, size_t ldc, size_t splitStride, int kLen)
{
    constexpr int TM = 64, TN = 64, TK = 32;
    __shared__ float As[2][TK][TM + 4];
    __shared__ float Bs[2][TK][TN + 4];

    const int tid = threadIdx.x;
    const int m0  = blockIdx.y * TM;
    const int n0  = blockIdx.x * TN;

    A += (size_t)m0 * lda + (size_t)blockIdx.z * kLen;
    B += (size_t)n0 * ldb + (size_t)blockIdx.z * kLen;
    C += (size_t)blockIdx.z * splitStride + (size_t)m0 * ldc + n0;

    const int lr  = tid >> 2;
    const int lc4 = tid & 3;
    const int tx  = tid & 15;
    const int ty  = tid >> 4;

    const float* Ald = A + (size_t)lr * lda + lc4 * 4;
    const float* Bld = B + (size_t)lr * ldb + lc4 * 4;

    float4 ra0 = *(const float4*)(Ald);
    float4 ra1 = *(const float4*)(Ald + 16);
    float4 rb0 = *(const float4*)(Bld);
    float4 rb1 = *(const float4*)(Bld + 16);

    float acc[4][4];
#pragma unroll
    for (int i = 0; i < 4; i++)
#pragma unroll
        for (int j = 0; j < 4; j++) acc[i][j] = 0.f;

    const int nk = kLen / TK;
    int buf = 0;

#define STORE_TILE(bf)                                                        \
    {   int kk0 = lc4 * 4;                                                    \
        As[bf][kk0+ 0][lr]=ra0.x; As[bf][kk0+ 1][lr]=ra0.y;                   \
        As[bf][kk0+ 2][lr]=ra0.z; As[bf][kk0+ 3][lr]=ra0.w;                   \
        As[bf][kk0+16][lr]=ra1.x; As[bf][kk0+17][lr]=ra1.y;                   \
        As[bf][kk0+18][lr]=ra1.z; As[bf][kk0+19][lr]=ra1.w;                   \
        Bs[bf][kk0+ 0][lr]=rb0.x; Bs[bf][kk0+ 1][lr]=rb0.y;                   \
        Bs[bf][kk0+ 2][lr]=rb0.z; Bs[bf][kk0+ 3][lr]=rb0.w;                   \
        Bs[bf][kk0+16][lr]=rb1.x; Bs[bf][kk0+17][lr]=rb1.y;                   \
        Bs[bf][kk0+18][lr]=rb1.z; Bs[bf][kk0+19][lr]=rb1.w; }

    STORE_TILE(0);
    __syncthreads();

    for (int kt = 0; kt < nk; kt++) {
        if (kt + 1 < nk) {
            const float* Ap = Ald + (kt + 1) * TK;
            const float* Bp = Bld + (kt + 1) * TK;
            ra0 = *(const float4*)(Ap);
            ra1 = *(const float4*)(Ap + 16);
            rb0 = *(const float4*)(Bp);
            rb1 = *(const float4*)(Bp + 16);
        }
#pragma unroll
        for (int k = 0; k < TK; k++) {
            float4 a = *(const float4*)&As[buf][k][ty * 4];
            float4 b = *(const float4*)&Bs[buf][k][tx * 4];
            acc[0][0]=fmaf(a.x,b.x,acc[0][0]); acc[0][1]=fmaf(a.x,b.y,acc[0][1]);
            acc[0][2]=fmaf(a.x,b.z,acc[0][2]); acc[0][3]=fmaf(a.x,b.w,acc[0][3]);
            acc[1][0]=fmaf(a.y,b.x,acc[1][0]); acc[1][1]=fmaf(a.y,b.y,acc[1][1]);
            acc[1][2]=fmaf(a.y,b.z,acc[1][2]); acc[1][3]=fmaf(a.y,b.w,acc[1][3]);
            acc[2][0]=fmaf(a.z,b.x,acc[2][0]); acc[2][1]=fmaf(a.z,b.y,acc[2][1]);
            acc[2][2]=fmaf(a.z,b.z,acc[2][2]); acc[2][3]=fmaf(a.z,b.w,acc[2][3]);
            acc[3][0]=fmaf(a.w,b.x,acc[3][0]); acc[3][1]=fmaf(a.w,b.y,acc[3][1]);
            acc[3][2]=fmaf(a.w,b.z,acc[3][2]); acc[3][3]=fmaf(a.w,b.w,acc[3][3]);
        }
        if (kt + 1 < nk) {
            STORE_TILE(buf ^ 1);
            __syncthreads();
            buf ^= 1;
        }
    }
#undef STORE_TILE

#pragma unroll
    for (int i = 0; i < 4; i++) {
        float4 o = make_float4(acc[i][0], acc[i][1], acc[i][2], acc[i][3]);
        *(float4*)(C + (size_t)(ty * 4 + i) * ldc + tx * 4) = o;
    }
}

// ---------------------------------------------------------------------------
// Setup kernels
// ---------------------------------------------------------------------------
__global__ void build_wcat(const float* __restrict__ W_ih,
                           const float* __restrict__ W_hh)
{
    size_t total = (size_t)NGATE * KCAT;
    for (size_t i = (size_t)blockIdx.x * blockDim.x + threadIdx.x; i < total;
         i += (size_t)gridDim.x * blockDim.x) {
        int j = (int)(i / KCAT);
        int k = (int)(i % KCAT);
        g_wcat[i] = (k < EMBD) ? W_ih[(size_t)j * EMBD + k]
                               : W_hh[(size_t)j * HH + (k - EMBD)];
    }
}

__global__ void init_state(const float* __restrict__ dec_init)
{
    int idx = blockIdx.x * blockDim.x + threadIdx.x;   // B*H
    int b = idx >> 10, j = idx & 1023;
    float h0 = dec_init[idx];
    g_hc[b * 2048 + j] = h0;
    g_xcat[b * KCAT + EMBD + j] = h0;
    g_c[idx] = dec_init[BB * HH + idx];
    if (j < EMBD) g_xcat[b * KCAT + j] = 0.f;
}

// ---------------------------------------------------------------------------
// LSTM cell (float4): sum GSPLIT gate partials + bias, apply nonlinearity
// ---------------------------------------------------------------------------
__device__ __forceinline__ float sigf(float x) { return 1.f / (1.f + expf(-x)); }

__global__ void __launch_bounds__(256)
lstm_cell(const float* __restrict__ b_lstm)
{
    int q = blockIdx.x * blockDim.x + threadIdx.x;     // 0..B*H/4-1
    int base = q * 4;
    int b = base >> 10, j = base & 1023;
    const float* gp = g_gpart + (size_t)b * NGATE;
    const size_t SP = (size_t)BB * NGATE;

    float4 ig = *(const float4*)&b_lstm[j];
    float4 fg = *(const float4*)&b_lstm[1024 + j];
    float4 gg = *(const float4*)&b_lstm[2048 + j];
    float4 og = *(const float4*)&b_lstm[3072 + j];
#pragma unroll
    for (int s = 0; s < GSPLIT; s++) {
        const float* p = gp + s * SP;
        float4 v;
        v = *(const float4*)&p[j];        ig.x+=v.x; ig.y+=v.y; ig.z+=v.z; ig.w+=v.w;
        v = *(const float4*)&p[1024 + j]; fg.x+=v.x; fg.y+=v.y; fg.z+=v.z; fg.w+=v.w;
        v = *(const float4*)&p[2048 + j]; gg.x+=v.x; gg.y+=v.y; gg.z+=v.z; gg.w+=v.w;
        v = *(const float4*)&p[3072 + j]; og.x+=v.x; og.y+=v.y; og.z+=v.z; og.w+=v.w;
    }
    float4 cold = *(const float4*)&g_c[base];
    float4 c, h;
    c.x = sigf(fg.x) * cold.x + sigf(ig.x) * tanhf(gg.x);
    c.y = sigf(fg.y) * cold.y + sigf(ig.y) * tanhf(gg.y);
    c.z = sigf(fg.z) * cold.z + sigf(ig.z) * tanhf(gg.z);
    c.w = sigf(fg.w) * cold.w + sigf(ig.w) * tanhf(gg.w);
    h.x = sigf(og.x) * tanhf(c.x);
    h.y = sigf(og.y) * tanhf(c.y);
    h.z = sigf(og.z) * tanhf(c.z);
    h.w = sigf(og.w) * tanhf(c.w);
    *(float4*)&g_c[base] = c;
    *(float4*)&g_hc[b * 2048 + j] = h;
    *(float4*)&g_xcat[b * KCAT + EMBD + j] = h;
}

// ---------------------------------------------------------------------------
// Attention scores: grid (16, B); one score row per warp (8 rows/block)
// ---------------------------------------------------------------------------
__global__ void __launch_bounds__(256)
attn_scores()
{
    int b = blockIdx.y;
    int tid = threadIdx.x, warp = tid >> 5, lane = tid & 31;
    __shared__ float4 sh4[HH / 4];

    const float4* h4 = (const float4*)&g_hc[b * 2048];
    sh4[tid] = h4[tid];                       // 256 float4 = 1024 floats
    __syncthreads();

    int s = blockIdx.x * 8 + warp;
    const float4* k4 = (const float4*)&g_keys[((size_t)b * SS + s) * HH];
    float acc = 0.f;
#pragma unroll
    for (int i = 0; i < 8; i++) {
        float4 kv = k4[lane + 32 * i];        // 8 independent loads in flight
        float4 hv = sh4[lane + 32 * i];
        acc = fmaf(kv.x, hv.x, acc);
        acc = fmaf(kv.y, hv.y, acc);
        acc = fmaf(kv.z, hv.z, acc);
        acc = fmaf(kv.w, hv.w, acc);
    }
#pragma unroll
    for (int o = 16; o; o >>= 1) acc += __shfl_xor_sync(0xffffffffu, acc, o);
    if (lane == 0) g_scores[b * SS + s] = acc;
}

// ---------------------------------------------------------------------------
// Attention context (softmax fused, recomputed per block): grid (4, B)
// ---------------------------------------------------------------------------
__global__ void __launch_bounds__(256)
attn_context(const float* __restrict__ enc, const int* __restrict__ enc_len)
{
    int b = blockIdx.y, e0 = blockIdx.x * 256;
    int tid = threadIdx.x, warp = tid >> 5, lane = tid & 31;
    __shared__ float sa[SS];
    __shared__ float red[8];
    __shared__ float bc;

    int len = enc_len[b];
    float v = -1e9f;
    if (tid < SS) {
        float s = g_scores[b * SS + tid];
        v = (tid < len) ? s : -1e9f;
        sa[tid] = v;
    }
    float m = v;
#pragma unroll
    for (int o = 16; o; o >>= 1) m = fmaxf(m, __shfl_xor_sync(0xffffffffu, m, o));
    if (lane == 0) red[warp] = m;
    __syncthreads();
    if (tid == 0) {
        float mm = red[0];
        for (int i = 1; i < 4; i++) mm = fmaxf(mm, red[i]);
        bc = mm;
    }
    __syncthreads();
    float mx = bc;

    float e = (tid < SS) ? expf(v - mx) : 0.f;
    float s2 = e;
#pragma unroll
    for (int o = 16; o; o >>= 1) s2 += __shfl_xor_sync(0xffffffffu, s2, o);
    __syncthreads();
    if (lane == 0) red[warp] = s2;
    __syncthreads();
    if (tid == 0) bc = red[0] + red[1] + red[2] + red[3];
    __syncthreads();
    float inv = 1.f / bc;
    if (tid < SS) sa[tid] = e * inv;
    __syncthreads();

    const float* ep = enc + ((size_t)b * SS) * EE + e0 + tid;
    float acc = 0.f;
    int s = 0;
    for (; s + 8 <= len; s += 8) {
        float x0 = ep[(size_t)(s + 0) * EE];
        float x1 = ep[(size_t)(s + 1) * EE];
        float x2 = ep[(size_t)(s + 2) * EE];
        float x3 = ep[(size_t)(s + 3) * EE];
        float x4 = ep[(size_t)(s + 4) * EE];
        float x5 = ep[(size_t)(s + 5) * EE];
        float x6 = ep[(size_t)(s + 6) * EE];
        float x7 = ep[(size_t)(s + 7) * EE];
        acc = fmaf(sa[s + 0], x0, acc);
        acc = fmaf(sa[s + 1], x1, acc);
        acc = fmaf(sa[s + 2], x2, acc);
        acc = fmaf(sa[s + 3], x3, acc);
        acc = fmaf(sa[s + 4], x4, acc);
        acc = fmaf(sa[s + 5], x5, acc);
        acc = fmaf(sa[s + 6], x6, acc);
        acc = fmaf(sa[s + 7], x7, acc);
    }
    for (; s < len; s++) acc = fmaf(sa[s], ep[(size_t)s * EE], acc);
    g_hc[b * 2048 + HH + e0 + tid] = acc;
}

// ---------------------------------------------------------------------------
// Reduce out-projection split-K partials (float4)
// ---------------------------------------------------------------------------
__global__ void __launch_bounds__(256)
reduce_dec()
{
    int q = blockIdx.x * blockDim.x + threadIdx.x;    // 0..B*EMBD/4-1
    float4 a = make_float4(0.f, 0.f, 0.f, 0.f);
#pragma unroll
    for (int s = 0; s < OSPLIT; s++) {
        float4 v = *(const float4*)&g_dpart[(size_t)s * BB * EMBD + q * 4];
        a.x += v.x; a.y += v.y; a.z += v.z; a.w += v.w;
    }
    *(float4*)&g_dec[q * 4] = a;
}

// ---------------------------------------------------------------------------
// Greedy argmax over logits row + embedding gather
// ---------------------------------------------------------------------------
__global__ void __launch_bounds__(1024)
argmax_embed(const float* __restrict__ logits, const float* __restrict__ emb, int t)
{
    int b = blockIdx.x;
    const float4* row4 = (const float4*)(logits + ((size_t)b * TT + t) * VV);
    int tid = threadIdx.x;

    float bv = -INFINITY;
    int   bi = 0x7fffffff;
#pragma unroll
    for (int j = 0; j < 8; j++) {
        int v4 = j * 1024 + tid;
        if (v4 < VV / 4) {
            float4 x = row4[v4];
            int base = v4 * 4;
            if (x.x > bv || (x.x == bv && base     < bi)) { bv = x.x; bi = base;     }
            if (x.y > bv || (x.y == bv && base + 1 < bi)) { bv = x.y; bi = base + 1; }
            if (x.z > bv || (x.z == bv && base + 2 < bi)) { bv = x.z; bi = base + 2; }
            if (x.w > bv || (x.w == bv && base + 3 < bi)) { bv = x.w; bi = base + 3; }
        }
    }
#pragma unroll
    for (int o = 16; o; o >>= 1) {
        float ov = __shfl_xor_sync(0xffffffffu, bv, o);
        int   oi = __shfl_xor_sync(0xffffffffu, bi, o);
        if (ov > bv || (ov == bv && oi < bi)) { bv = ov; bi = oi; }
    }
    __shared__ float sv[32];
    __shared__ int   si[32];
    __shared__ int   ssym;
    int warp = tid >> 5, lane = tid & 31;
    if (lane == 0) { sv[warp] = bv; si[warp] = bi; }
    __syncthreads();
    if (warp == 0) {
        bv = sv[lane]; bi = si[lane];
#pragma unroll
        for (int o = 16; o; o >>= 1) {
            float ov = __shfl_xor_sync(0xffffffffu, bv, o);
            int   oi = __shfl_xor_sync(0xffffffffu, bi, o);
            if (ov > bv || (ov == bv && oi < bi)) { bv = ov; bi = oi; }
        }
        if (lane == 0) ssym = bi;
    }
    __syncthreads();
    int sym = ssym;
    if (tid < EMBD / 4) {
        const float4* er = (const float4*)(emb + (size_t)sym * EMBD);
        ((float4*)&g_xcat[b * KCAT])[tid] = er[tid];
    }
}

// ---------------------------------------------------------------------------
// Fused in-place log-softmax over each [VV] row of d_out
// ---------------------------------------------------------------------------
__global__ void __launch_bounds__(1024)
logsoftmax_rows(float* __restrict__ out)
{
    float* p = out + (size_t)blockIdx.x * VV;
    int tid = threadIdx.x;

    float x[32];
    float mx = -INFINITY;
#pragma unroll
    for (int i = 0; i < 32; i++) {
        int v = tid + (i << 10);
        x[i] = (v < VV) ? p[v] : -INFINITY;
        mx = fmaxf(mx, x[i]);
    }
    __shared__ float red[32];
    __shared__ float bc;
#pragma unroll
    for (int o = 16; o; o >>= 1) mx = fmaxf(mx, __shfl_xor_sync(0xffffffffu, mx, o));
    if ((tid & 31) == 0) red[tid >> 5] = mx;
    __syncthreads();
    if (tid < 32) {
        float m = red[tid];
#pragma unroll
        for (int o = 16; o; o >>= 1) m = fmaxf(m, __shfl_xor_sync(0xffffffffu, m, o));
        if (tid == 0) bc = m;
    }
    __syncthreads();
    float M = bc;

    float s = 0.f;
#pragma unroll
    for (int i = 0; i < 32; i++) s += expf(x[i] - M);
    __syncthreads();
#pragma unroll
    for (int o = 16; o; o >>= 1) s += __shfl_xor_sync(0xffffffffu, s, o);
    if ((tid & 31) == 0) red[tid >> 5] = s;
    __syncthreads();
    if (tid < 32) {
        float m = red[tid];
#pragma unroll
        for (int o = 16; o; o >>= 1) m += __shfl_xor_sync(0xffffffffu, m, o);
        if (tid == 0) bc = m;
    }
    __syncthreads();
    float lz = M + logf(bc);
#pragma unroll
    for (int i = 0; i < 32; i++) {
        int v = tid + (i << 10);
        if (v < VV) p[v] = x[i] - lz;
    }
}

__global__ void fill_tail(float* __restrict__ p, long n, float val)
{
    long i = (long)blockIdx.x * blockDim.x + threadIdx.x;
    if (i < n) p[i] = val;
}

// ---------------------------------------------------------------------------
// Launch
// ---------------------------------------------------------------------------
extern "C" void kernel_launch(void* const* d_in, const int* in_sizes, int n_in,
                              void* d_out, int out_size)
{
    const float* dec_init  = (const float*)d_in[0];
    const float* enc       = (const float*)d_in[1];
    const int*   enc_len   = (const int*)d_in[2];
    /* d_in[3] = tgt (unused in eval mode) */
    const float* W_ih      = (const float*)d_in[4];
    const float* W_hh      = (const float*)d_in[5];
    const float* b_lstm    = (const float*)d_in[6];
    const float* W_attproj = (const float*)d_in[7];
    const float* W_out     = (const float*)d_in[8];
    const float* W_vocab   = (const float*)d_in[9];
    const float* emb       = (const float*)d_in[10];
    float* out = (float*)d_out;

    void *p_keys, *p_wcat, *p_xcat, *p_hc, *p_gpart, *p_dpart, *p_dec;
    cudaGetSymbolAddress(&p_keys,  g_keys);
    cudaGetSymbolAddress(&p_wcat,  g_wcat);
    cudaGetSymbolAddress(&p_xcat,  g_xcat);
    cudaGetSymbolAddress(&p_hc,    g_hc);
    cudaGetSymbolAddress(&p_gpart, g_gpart);
    cudaGetSymbolAddress(&p_dpart, g_dpart);
    cudaGetSymbolAddress(&p_dec,   g_dec);

    // one-time setup
    build_wcat<<<2048, 256>>>(W_ih, W_hh);
    init_state<<<(BB * HH) / 256, 256>>>(dec_init);
    // keys[B*S, H] = enc[B*S, E] @ W_attproj^T   (grid 8 x 128 = 1024 blocks)
    sgemm128<<<dim3(HH / 128, (BB * SS) / 64, 1), 256>>>(
        enc, EE, W_attproj, EE, (float*)p_keys, HH, 0, EE);

    for (int t = 0; t < TT; t++) {
        // gates partials: split-K x8  (32 x 8 = 256 blocks, kLen=192)
        sgemm128<<<dim3(NGATE / 128, 1, GSPLIT), 256>>>(
            (const float*)p_xcat, KCAT, (const float*)p_wcat, KCAT,
            (float*)p_gpart, NGATE, (size_t)BB * NGATE, KCAT / GSPLIT);
        lstm_cell<<<(BB * HH / 4) / 256, 256>>>(b_lstm);
        attn_scores<<<dim3(16, BB), 256>>>();
        attn_context<<<dim3(4, BB), 256>>>(enc, enc_len);
        // dec partials: split-K x32  (8 x 32 = 256 blocks, kLen=64)
        sgemm64<<<dim3(EMBD / 64, 1, OSPLIT), 256>>>(
            (const float*)p_hc, 2048, W_out, 2048,
            (float*)p_dpart, EMBD, (size_t)BB * EMBD, 2048 / OSPLIT);
        reduce_dec<<<(BB * EMBD / 4) / 256, 256>>>();
        // vocab logits straight into d_out[b, t, :]  (250 blocks)
        sgemm128<<<dim3(VV / 128, 1, 1), 256>>>(
            (const float*)p_dec, EMBD, W_vocab, EMBD,
            out + (size_t)t * VV, (size_t)TT * VV, 0, EMBD);
        argmax_embed<<<BB, 1024>>>(out, emb, t);
    }

    // final log-softmax in place over all B*T rows
    logsoftmax_rows<<<BB * TT, 1024>>>(out);

    // tgt_len output: always T (== 50) per the reference's final where()
    long extra = (long)out_size - (long)BB * TT * VV;
    if (extra > 0)
        fill_tail<<<(unsigned)((extra + 255) / 256), 256>>>(
            out + (size_t)BB * TT * VV, extra, 50.0f);
}

// round 11
// speedup vs baseline: 2.8832x; 1.0174x over previous
#include <cuda_runtime.h>
#include <math.h>

// Problem constants (fixed by the reference)
#define BB   64
#define SS   128
#define HH   1024
#define EE   1024
#define EMBD 512
#define VV   32000
#define TT   50
#define KCAT 1536          // EMBD + HH
#define NGATE 4096         // 4*HH
#define GSPLIT 8           // split-K for gates GEMM (KCAT/8 = 192)
#define OSPLIT 32          // split-K for out-projection GEMM (2048/32 = 64)

typedef unsigned long long u64;

// ---- packed fp32x2 FMA (Blackwell): 2 IEEE fp32 FMAs per instruction ------
__device__ __forceinline__ u64 pack2(float v) {
    u64 r; asm("mov.b64 %0, {%1, %1};" : "=l"(r) : "f"(v)); return r;
}
__device__ __forceinline__ void ffma2(u64 &d, u64 a, u64 b) {
    asm("fma.rn.f32x2 %0, %1, %2, %0;" : "+l"(d) : "l"(a), "l"(b));
}
__device__ __forceinline__ float2 unpack2(u64 v) {
    float2 f; asm("mov.b64 {%0, %1}, %2;" : "=f"(f.x), "=f"(f.y) : "l"(v)); return f;
}

// ---------------------------------------------------------------------------
// Device scratch (static device globals — no allocation)
// ---------------------------------------------------------------------------
__device__ float g_keys[(size_t)BB * SS * HH];       // att keys [B,S,H]
__device__ float g_wcat[(size_t)NGATE * KCAT];       // [W_ih | W_hh]
__device__ float g_xcat[BB * KCAT];                  // [prev_emb | h]
__device__ float g_hc[BB * 2048];                    // [h | c_t]
__device__ float g_c[BB * HH];                       // LSTM cell state
__device__ float g_gpart[GSPLIT * BB * NGATE];       // gates partials
__device__ float g_dpart[OSPLIT * BB * EMBD];        // out-proj partials
__device__ float g_dec[BB * EMBD];                   // out-projection result
__device__ float g_scores[BB * SS];                  // attention scores

// ---------------------------------------------------------------------------
// FFMA2 SGEMM:  C[M,N] = A[M,K]*B[N,K]^T
// Block tile 64x128, TK=32, 256 threads, 8x4 micro-tile.
// Accumulators pair adjacent M-rows -> a-pairs load free as ulonglong2 from
// the k-major As tile; b values duplicated with one mov.b64 each (ALU pipe).
// Single __syncthreads per k-tile (store targets opposite buffer).
// ---------------------------------------------------------------------------
__global__ void __launch_bounds__(256)
sgemm128(const float* __restrict__ A, int lda,
         const float* __restrict__ B, int ldb,
         float* __restrict__ C, size_t ldc, size_t splitStride, int kLen)
{
    constexpr int TM = 64, TN = 128, TK = 32;
    __shared__ float As[2][TK][TM + 4];
    __shared__ float Bs[2][TK][TN + 4];

    const int tid = threadIdx.x;
    const int m0  = blockIdx.y * TM;
    const int n0  = blockIdx.x * TN;

    A += (size_t)m0 * lda + (size_t)blockIdx.z * kLen;
    B += (size_t)n0 * ldb + (size_t)blockIdx.z * kLen;
    C += (size_t)blockIdx.z * splitStride + (size_t)m0 * ldc + n0;

    // loaders
    const int ar = tid >> 2;            // A row 0..63
    const int ak = (tid & 3) * 4;       // A k base {0,4,8,12} (+16)
    const int br = tid >> 1;            // B row 0..127
    const int bk = (tid & 1) * 4;       // B k base {0,4} (+8,+16,+24)
    const float* Ald = A + (size_t)ar * lda + ak;
    const float* Bld = B + (size_t)br * ldb + bk;

    float4 ra0 = *(const float4*)(Ald);
    float4 ra1 = *(const float4*)(Ald + 16);
    float4 rb0 = *(const float4*)(Bld);
    float4 rb1 = *(const float4*)(Bld + 8);
    float4 rb2 = *(const float4*)(Bld + 16);
    float4 rb3 = *(const float4*)(Bld + 24);

    // compute mapping: 8 rows x 4 cols per thread
    const int rg = tid >> 5;            // warp id 0..7  -> rows rg*8..rg*8+7
    const int cg = tid & 31;            // lane          -> cols cg*4..cg*4+3

    // accP[p][j] = (acc[2p][j], acc[2p+1][j]) packed fp32x2; 0ULL == (0.f,0.f)
    u64 accP[4][4];
#pragma unroll
    for (int i = 0; i < 4; i++)
#pragma unroll
        for (int j = 0; j < 4; j++) accP[i][j] = 0ULL;

    const int nk = kLen / TK;
    int buf = 0;

#define STORE_TILE128(bf)                                                     \
    {   As[bf][ak+ 0][ar]=ra0.x; As[bf][ak+ 1][ar]=ra0.y;                     \
        As[bf][ak+ 2][ar]=ra0.z; As[bf][ak+ 3][ar]=ra0.w;                     \
        As[bf][ak+16][ar]=ra1.x; As[bf][ak+17][ar]=ra1.y;                     \
        As[bf][ak+18][ar]=ra1.z; As[bf][ak+19][ar]=ra1.w;                     \
        Bs[bf][bk+ 0][br]=rb0.x; Bs[bf][bk+ 1][br]=rb0.y;                     \
        Bs[bf][bk+ 2][br]=rb0.z; Bs[bf][bk+ 3][br]=rb0.w;                     \
        Bs[bf][bk+ 8][br]=rb1.x; Bs[bf][bk+ 9][br]=rb1.y;                     \
        Bs[bf][bk+10][br]=rb1.z; Bs[bf][bk+11][br]=rb1.w;                     \
        Bs[bf][bk+16][br]=rb2.x; Bs[bf][bk+17][br]=rb2.y;                     \
        Bs[bf][bk+18][br]=rb2.z; Bs[bf][bk+19][br]=rb2.w;                     \
        Bs[bf][bk+24][br]=rb3.x; Bs[bf][bk+25][br]=rb3.y;                     \
        Bs[bf][bk+26][br]=rb3.z; Bs[bf][bk+27][br]=rb3.w; }

    STORE_TILE128(0);
    __syncthreads();

    for (int kt = 0; kt < nk; kt++) {
        if (kt + 1 < nk) {                      // prefetch next tile to regs
            const float* Ap = Ald + (kt + 1) * TK;
            const float* Bp = Bld + (kt + 1) * TK;
            ra0 = *(const float4*)(Ap);
            ra1 = *(const float4*)(Ap + 16);
            rb0 = *(const float4*)(Bp);
            rb1 = *(const float4*)(Bp + 8);
            rb2 = *(const float4*)(Bp + 16);
            rb3 = *(const float4*)(Bp + 24);
        }
#pragma unroll
        for (int k = 0; k < TK; k++) {
            // row pairs: 16B-aligned (row stride 68 floats = 272B = 17*16)
            ulonglong2 aLo = *(const ulonglong2*)&As[buf][k][rg * 8];     // rows 0-3
            ulonglong2 aHi = *(const ulonglong2*)&As[buf][k][rg * 8 + 4]; // rows 4-7
            float4 b = *(const float4*)&Bs[buf][k][cg * 4];               // conflict-free
            u64 b0 = pack2(b.x), b1 = pack2(b.y), b2 = pack2(b.z), b3 = pack2(b.w);
            ffma2(accP[0][0], aLo.x, b0); ffma2(accP[0][1], aLo.x, b1);
            ffma2(accP[0][2], aLo.x, b2); ffma2(accP[0][3], aLo.x, b3);
            ffma2(accP[1][0], aLo.y, b0); ffma2(accP[1][1], aLo.y, b1);
            ffma2(accP[1][2], aLo.y, b2); ffma2(accP[1][3], aLo.y, b3);
            ffma2(accP[2][0], aHi.x, b0); ffma2(accP[2][1], aHi.x, b1);
            ffma2(accP[2][2], aHi.x, b2); ffma2(accP[2][3], aHi.x, b3);
            ffma2(accP[3][0], aHi.y, b0); ffma2(accP[3][1], aHi.y, b1);
            ffma2(accP[3][2], aHi.y, b2); ffma2(accP[3][3], aHi.y, b3);
        }
        if (kt + 1 < nk) {
            STORE_TILE128(buf ^ 1);    // opposite buffer: safe without pre-sync
            __syncthreads();
            buf ^= 1;
        }
    }
#undef STORE_TILE128

#pragma unroll
    for (int p = 0; p < 4; p++) {
        float2 c0 = unpack2(accP[p][0]);
        float2 c1 = unpack2(accP[p][1]);
        float2 c2 = unpack2(accP[p][2]);
        float2 c3 = unpack2(accP[p][3]);
        float4 lo = make_float4(c0.x, c1.x, c2.x, c3.x);   // row 2p
        float4 hi = make_float4(c0.y, c1.y, c2.y, c3.y);   // row 2p+1
        *(float4*)(C + (size_t)(rg * 8 + 2 * p)     * ldc + cg * 4) = lo;
        *(float4*)(C + (size_t)(rg * 8 + 2 * p + 1) * ldc + cg * 4) = hi;
    }
}

// ---------------------------------------------------------------------------
// Small FFMA2 SGEMM (TN=64, 4x4 micro-tile) — only the tiny out-projection
// ---------------------------------------------------------------------------
__global__ void __launch_bounds__(256)
sgemm64(const float* __restrict__ A, int lda,
        const float* __restrict__ B, int ldb,
        float* __restrict__ C, size_t ldc, size_t splitStride, int kLen)
{
    constexpr int TM = 64, TN = 64, TK = 32;
    __shared__ float As[2][TK][TM + 4];
    __shared__ float Bs[2][TK][TN + 4];

    const int tid = threadIdx.x;
    const int m0  = blockIdx.y * TM;
    const int n0  = blockIdx.x * TN;

    A += (size_t)m0 * lda + (size_t)blockIdx.z * kLen;
    B += (size_t)n0 * ldb + (size_t)blockIdx.z * kLen;
    C += (size_t)blockIdx.z * splitStride + (size_t)m0 * ldc + n0;

    const int lr  = tid >> 2;
    const int lc4 = tid & 3;
    const int tx  = tid & 15;
    const int ty  = tid >> 4;

    const float* Ald = A + (size_t)lr * lda + lc4 * 4;
    const float* Bld = B + (size_t)lr * ldb + lc4 * 4;

    float4 ra0 = *(const float4*)(Ald);
    float4 ra1 = *(const float4*)(Ald + 16);
    float4 rb0 = *(const float4*)(Bld);
    float4 rb1 = *(const float4*)(Bld + 16);

    u64 accP[2][4];       // pairs over the 4 rows
#pragma unroll
    for (int i = 0; i < 2; i++)
#pragma unroll
        for (int j = 0; j < 4; j++) accP[i][j] = 0ULL;

    const int nk = kLen / TK;
    int buf = 0;

#define STORE_TILE(bf)                                                        \
    {   int kk0 = lc4 * 4;                                                    \
        As[bf][kk0+ 0][lr]=ra0.x; As[bf][kk0+ 1][lr]=ra0.y;                   \
        As[bf][kk0+ 2][lr]=ra0.z; As[bf][kk0+ 3][lr]=ra0.w;                   \
        As[bf][kk0+16][lr]=ra1.x; As[bf][kk0+17][lr]=ra1.y;                   \
        As[bf][kk0+18][lr]=ra1.z; As[bf][kk0+19][lr]=ra1.w;                   \
        Bs[bf][kk0+ 0][lr]=rb0.x; Bs[bf][kk0+ 1][lr]=rb0.y;                   \
        Bs[bf][kk0+ 2][lr]=rb0.z; Bs[bf][kk0+ 3][lr]=rb0.w;                   \
        Bs[bf][kk0+16][lr]=rb1.x; Bs[bf][kk0+17][lr]=rb1.y;                   \
        Bs[bf][kk0+18][lr]=rb1.z; Bs[bf][kk0+19][lr]=rb1.w; }

    STORE_TILE(0);
    __syncthreads();

    for (int kt = 0; kt < nk; kt++) {
        if (kt + 1 < nk) {
            const float* Ap = Ald + (kt + 1) * TK;
            const float* Bp = Bld + (kt + 1) * TK;
            ra0 = *(const float4*)(Ap);
            ra1 = *(const float4*)(Ap + 16);
            rb0 = *(const float4*)(Bp);
            rb1 = *(const float4*)(Bp + 16);
        }
#pragma unroll
        for (int k = 0; k < TK; k++) {
            ulonglong2 aP = *(const ulonglong2*)&As[buf][k][ty * 4];  // 16B aligned
            float4 b = *(const float4*)&Bs[buf][k][tx * 4];
            u64 b0 = pack2(b.x), b1 = pack2(b.y), b2 = pack2(b.z), b3 = pack2(b.w);
            ffma2(accP[0][0], aP.x, b0); ffma2(accP[0][1], aP.x, b1);
            ffma2(accP[0][2], aP.x, b2); ffma2(accP[0][3], aP.x, b3);
            ffma2(accP[1][0], aP.y, b0); ffma2(accP[1][1], aP.y, b1);
            ffma2(accP[1][2], aP.y, b2); ffma2(accP[1][3], aP.y, b3);
        }
        if (kt + 1 < nk) {
            STORE_TILE(buf ^ 1);
            __syncthreads();
            buf ^= 1;
        }
    }
#undef STORE_TILE

#pragma unroll
    for (int p = 0; p < 2; p++) {
        float2 c0 = unpack2(accP[p][0]);
        float2 c1 = unpack2(accP[p][1]);
        float2 c2 = unpack2(accP[p][2]);
        float2 c3 = unpack2(accP[p][3]);
        float4 lo = make_float4(c0.x, c1.x, c2.x, c3.x);
        float4 hi = make_float4(c0.y, c1.y, c2.y, c3.y);
        *(float4*)(C + (size_t)(ty * 4 + 2 * p)     * ldc + tx * 4) = lo;
        *(float4*)(C + (size_t)(ty * 4 + 2 * p + 1) * ldc + tx * 4) = hi;
    }
}

// ---------------------------------------------------------------------------
// Setup kernels
// ---------------------------------------------------------------------------
__global__ void build_wcat(const float* __restrict__ W_ih,
                           const float* __restrict__ W_hh)
{
    size_t total = (size_t)NGATE * KCAT;
    for (size_t i = (size_t)blockIdx.x * blockDim.x + threadIdx.x; i < total;
         i += (size_t)gridDim.x * blockDim.x) {
        int j = (int)(i / KCAT);
        int k = (int)(i % KCAT);
        g_wcat[i] = (k < EMBD) ? W_ih[(size_t)j * EMBD + k]
                               : W_hh[(size_t)j * HH + (k - EMBD)];
    }
}

__global__ void init_state(const float* __restrict__ dec_init)
{
    int idx = blockIdx.x * blockDim.x + threadIdx.x;   // B*H
    int b = idx >> 10, j = idx & 1023;
    float h0 = dec_init[idx];
    g_hc[b * 2048 + j] = h0;
    g_xcat[b * KCAT + EMBD + j] = h0;
    g_c[idx] = dec_init[BB * HH + idx];
    if (j < EMBD) g_xcat[b * KCAT + j] = 0.f;
}

// ---------------------------------------------------------------------------
// LSTM cell (float4): sum GSPLIT gate partials + bias, apply nonlinearity
// ---------------------------------------------------------------------------
__device__ __forceinline__ float sigf(float x) { return 1.f / (1.f + expf(-x)); }

__global__ void __launch_bounds__(256)
lstm_cell(const float* __restrict__ b_lstm)
{
    int q = blockIdx.x * blockDim.x + threadIdx.x;     // 0..B*H/4-1
    int base = q * 4;
    int b = base >> 10, j = base & 1023;
    const float* gp = g_gpart + (size_t)b * NGATE;
    const size_t SP = (size_t)BB * NGATE;

    float4 ig = *(const float4*)&b_lstm[j];
    float4 fg = *(const float4*)&b_lstm[1024 + j];
    float4 gg = *(const float4*)&b_lstm[2048 + j];
    float4 og = *(const float4*)&b_lstm[3072 + j];
#pragma unroll
    for (int s = 0; s < GSPLIT; s++) {
        const float* p = gp + s * SP;
        float4 v;
        v = *(const float4*)&p[j];        ig.x+=v.x; ig.y+=v.y; ig.z+=v.z; ig.w+=v.w;
        v = *(const float4*)&p[1024 + j]; fg.x+=v.x; fg.y+=v.y; fg.z+=v.z; fg.w+=v.w;
        v = *(const float4*)&p[2048 + j]; gg.x+=v.x; gg.y+=v.y; gg.z+=v.z; gg.w+=v.w;
        v = *(const float4*)&p[3072 + j]; og.x+=v.x; og.y+=v.y; og.z+=v.z; og.w+=v.w;
    }
    float4 cold = *(const float4*)&g_c[base];
    float4 c, h;
    c.x = sigf(fg.x) * cold.x + sigf(ig.x) * tanhf(gg.x);
    c.y = sigf(fg.y) * cold.y + sigf(ig.y) * tanhf(gg.y);
    c.z = sigf(fg.z) * cold.z + sigf(ig.z) * tanhf(gg.z);
    c.w = sigf(fg.w) * cold.w + sigf(ig.w) * tanhf(gg.w);
    h.x = sigf(og.x) * tanhf(c.x);
    h.y = sigf(og.y) * tanhf(c.y);
    h.z = sigf(og.z) * tanhf(c.z);
    h.w = sigf(og.w) * tanhf(c.w);
    *(float4*)&g_c[base] = c;
    *(float4*)&g_hc[b * 2048 + j] = h;
    *(float4*)&g_xcat[b * KCAT + EMBD + j] = h;
}

// ---------------------------------------------------------------------------
// Attention scores: grid (16, B); one score row per warp (8 rows/block)
// ---------------------------------------------------------------------------
__global__ void __launch_bounds__(256)
attn_scores()
{
    int b = blockIdx.y;
    int tid = threadIdx.x, warp = tid >> 5, lane = tid & 31;
    __shared__ float4 sh4[HH / 4];

    const float4* h4 = (const float4*)&g_hc[b * 2048];
    sh4[tid] = h4[tid];                       // 256 float4 = 1024 floats
    __syncthreads();

    int s = blockIdx.x * 8 + warp;
    const float4* k4 = (const float4*)&g_keys[((size_t)b * SS + s) * HH];
    float acc = 0.f;
#pragma unroll
    for (int i = 0; i < 8; i++) {
        float4 kv = k4[lane + 32 * i];        // 8 independent loads in flight
        float4 hv = sh4[lane + 32 * i];
        acc = fmaf(kv.x, hv.x, acc);
        acc = fmaf(kv.y, hv.y, acc);
        acc = fmaf(kv.z, hv.z, acc);
        acc = fmaf(kv.w, hv.w, acc);
    }
#pragma unroll
    for (int o = 16; o; o >>= 1) acc += __shfl_xor_sync(0xffffffffu, acc, o);
    if (lane == 0) g_scores[b * SS + s] = acc;
}

// ---------------------------------------------------------------------------
// Attention context (softmax fused, recomputed per block): grid (4, B)
// ---------------------------------------------------------------------------
__global__ void __launch_bounds__(256)
attn_context(const float* __restrict__ enc, const int* __restrict__ enc_len)
{
    int b = blockIdx.y, e0 = blockIdx.x * 256;
    int tid = threadIdx.x, warp = tid >> 5, lane = tid & 31;
    __shared__ float sa[SS];
    __shared__ float red[8];
    __shared__ float bc;

    int len = enc_len[b];
    float v = -1e9f;
    if (tid < SS) {
        float s = g_scores[b * SS + tid];
        v = (tid < len) ? s : -1e9f;
        sa[tid] = v;
    }
    float m = v;
#pragma unroll
    for (int o = 16; o; o >>= 1) m = fmaxf(m, __shfl_xor_sync(0xffffffffu, m, o));
    if (lane == 0) red[warp] = m;
    __syncthreads();
    if (tid == 0) {
        float mm = red[0];
        for (int i = 1; i < 4; i++) mm = fmaxf(mm, red[i]);
        bc = mm;
    }
    __syncthreads();
    float mx = bc;

    float e = (tid < SS) ? expf(v - mx) : 0.f;
    float s2 = e;
#pragma unroll
    for (int o = 16; o; o >>= 1) s2 += __shfl_xor_sync(0xffffffffu, s2, o);
    __syncthreads();
    if (lane == 0) red[warp] = s2;
    __syncthreads();
    if (tid == 0) bc = red[0] + red[1] + red[2] + red[3];
    __syncthreads();
    float inv = 1.f / bc;
    if (tid < SS) sa[tid] = e * inv;
    __syncthreads();

    const float* ep = enc + ((size_t)b * SS) * EE + e0 + tid;
    float acc = 0.f;
    int s = 0;
    for (; s + 8 <= len; s += 8) {
        float x0 = ep[(size_t)(s + 0) * EE];
        float x1 = ep[(size_t)(s + 1) * EE];
        float x2 = ep[(size_t)(s + 2) * EE];
        float x3 = ep[(size_t)(s + 3) * EE];
        float x4 = ep[(size_t)(s + 4) * EE];
        float x5 = ep[(size_t)(s + 5) * EE];
        float x6 = ep[(size_t)(s + 6) * EE];
        float x7 = ep[(size_t)(s + 7) * EE];
        acc = fmaf(sa[s + 0], x0, acc);
        acc = fmaf(sa[s + 1], x1, acc);
        acc = fmaf(sa[s + 2], x2, acc);
        acc = fmaf(sa[s + 3], x3, acc);
        acc = fmaf(sa[s + 4], x4, acc);
        acc = fmaf(sa[s + 5], x5, acc);
        acc = fmaf(sa[s + 6], x6, acc);
        acc = fmaf(sa[s + 7], x7, acc);
    }
    for (; s < len; s++) acc = fmaf(sa[s], ep[(size_t)s * EE], acc);
    g_hc[b * 2048 + HH + e0 + tid] = acc;
}

// ---------------------------------------------------------------------------
// Reduce out-projection split-K partials (float4)
// ---------------------------------------------------------------------------
__global__ void __launch_bounds__(256)
reduce_dec()
{
    int q = blockIdx.x * blockDim.x + threadIdx.x;    // 0..B*EMBD/4-1
    float4 a = make_float4(0.f, 0.f, 0.f, 0.f);
#pragma unroll
    for (int s = 0; s < OSPLIT; s++) {
        float4 v = *(const float4*)&g_dpart[(size_t)s * BB * EMBD + q * 4];
        a.x += v.x; a.y += v.y; a.z += v.z; a.w += v.w;
    }
    *(float4*)&g_dec[q * 4] = a;
}

// ---------------------------------------------------------------------------
// Greedy argmax over logits row + embedding gather
// ---------------------------------------------------------------------------
__global__ void __launch_bounds__(1024)
argmax_embed(const float* __restrict__ logits, const float* __restrict__ emb, int t)
{
    int b = blockIdx.x;
    const float4* row4 = (const float4*)(logits + ((size_t)b * TT + t) * VV);
    int tid = threadIdx.x;

    float bv = -INFINITY;
    int   bi = 0x7fffffff;
#pragma unroll
    for (int j = 0; j < 8; j++) {
        int v4 = j * 1024 + tid;
        if (v4 < VV / 4) {
            float4 x = row4[v4];
            int base = v4 * 4;
            if (x.x > bv || (x.x == bv && base     < bi)) { bv = x.x; bi = base;     }
            if (x.y > bv || (x.y == bv && base + 1 < bi)) { bv = x.y; bi = base + 1; }
            if (x.z > bv || (x.z == bv && base + 2 < bi)) { bv = x.z; bi = base + 2; }
            if (x.w > bv || (x.w == bv && base + 3 < bi)) { bv = x.w; bi = base + 3; }
        }
    }
#pragma unroll
    for (int o = 16; o; o >>= 1) {
        float ov = __shfl_xor_sync(0xffffffffu, bv, o);
        int   oi = __shfl_xor_sync(0xffffffffu, bi, o);
        if (ov > bv || (ov == bv && oi < bi)) { bv = ov; bi = oi; }
    }
    __shared__ float sv[32];
    __shared__ int   si[32];
    __shared__ int   ssym;
    int warp = tid >> 5, lane = tid & 31;
    if (lane == 0) { sv[warp] = bv; si[warp] = bi; }
    __syncthreads();
    if (warp == 0) {
        bv = sv[lane]; bi = si[lane];
#pragma unroll
        for (int o = 16; o; o >>= 1) {
            float ov = __shfl_xor_sync(0xffffffffu, bv, o);
            int   oi = __shfl_xor_sync(0xffffffffu, bi, o);
            if (ov > bv || (ov == bv && oi < bi)) { bv = ov; bi = oi; }
        }
        if (lane == 0) ssym = bi;
    }
    __syncthreads();
    int sym = ssym;
    if (tid < EMBD / 4) {
        const float4* er = (const float4*)(emb + (size_t)sym * EMBD);
        ((float4*)&g_xcat[b * KCAT])[tid] = er[tid];
    }
}

// ---------------------------------------------------------------------------
// Fused in-place log-softmax over each [VV] row of d_out
// ---------------------------------------------------------------------------
__global__ void __launch_bounds__(1024)
logsoftmax_rows(float* __restrict__ out)
{
    float* p = out + (size_t)blockIdx.x * VV;
    int tid = threadIdx.x;

    float x[32];
    float mx = -INFINITY;
#pragma unroll
    for (int i = 0; i < 32; i++) {
        int v = tid + (i << 10);
        x[i] = (v < VV) ? p[v] : -INFINITY;
        mx = fmaxf(mx, x[i]);
    }
    __shared__ float red[32];
    __shared__ float bc;
#pragma unroll
    for (int o = 16; o; o >>= 1) mx = fmaxf(mx, __shfl_xor_sync(0xffffffffu, mx, o));
    if ((tid & 31) == 0) red[tid >> 5] = mx;
    __syncthreads();
    if (tid < 32) {
        float m = red[tid];
#pragma unroll
        for (int o = 16; o; o >>= 1) m = fmaxf(m, __shfl_xor_sync(0xffffffffu, m, o));
        if (tid == 0) bc = m;
    }
    __syncthreads();
    float M = bc;

    float s = 0.f;
#pragma unroll
    for (int i = 0; i < 32; i++) s += expf(x[i] - M);
    __syncthreads();
#pragma unroll
    for (int o = 16; o; o >>= 1) s += __shfl_xor_sync(0xffffffffu, s, o);
    if ((tid & 31) == 0) red[tid >> 5] = s;
    __syncthreads();
    if (tid < 32) {
        float m = red[tid];
#pragma unroll
        for (int o = 16; o; o >>= 1) m += __shfl_xor_sync(0xffffffffu, m, o);
        if (tid == 0) bc = m;
    }
    __syncthreads();
    float lz = M + logf(bc);
#pragma unroll
    for (int i = 0; i < 32; i++) {
        int v = tid + (i << 10);
        if (v < VV) p[v] = x[i] - lz;
    }
}

__global__ void fill_tail(float* __restrict__ p, long n, float val)
{
    long i = (long)blockIdx.x * blockDim.x + threadIdx.x;
    if (i < n) p[i] = val;
}

// ---------------------------------------------------------------------------
// Launch
// ---------------------------------------------------------------------------
extern "C" void kernel_launch(void* const* d_in, const int* in_sizes, int n_in,
                              void* d_out, int out_size)
{
    const float* dec_init  = (const float*)d_in[0];
    const float* enc       = (const float*)d_in[1];
    const int*   enc_len   = (const int*)d_in[2];
    /* d_in[3] = tgt (unused in eval mode) */
    const float* W_ih      = (const float*)d_in[4];
    const float* W_hh      = (const float*)d_in[5];
    const float* b_lstm    = (const float*)d_in[6];
    const float* W_attproj = (const float*)d_in[7];
    const float* W_out     = (const float*)d_in[8];
    const float* W_vocab   = (const float*)d_in[9];
    const float* emb       = (const float*)d_in[10];
    float* out = (float*)d_out;

    void *p_keys, *p_wcat, *p_xcat, *p_hc, *p_gpart, *p_dpart, *p_dec;
    cudaGetSymbolAddress(&p_keys,  g_keys);
    cudaGetSymbolAddress(&p_wcat,  g_wcat);
    cudaGetSymbolAddress(&p_xcat,  g_xcat);
    cudaGetSymbolAddress(&p_hc,    g_hc);
    cudaGetSymbolAddress(&p_gpart, g_gpart);
    cudaGetSymbolAddress(&p_dpart, g_dpart);
    cudaGetSymbolAddress(&p_dec,   g_dec);

    // one-time setup
    build_wcat<<<2048, 256>>>(W_ih, W_hh);
    init_state<<<(BB * HH) / 256, 256>>>(dec_init);
    // keys[B*S, H] = enc[B*S, E] @ W_attproj^T   (grid 8 x 128 = 1024 blocks)
    sgemm128<<<dim3(HH / 128, (BB * SS) / 64, 1), 256>>>(
        enc, EE, W_attproj, EE, (float*)p_keys, HH, 0, EE);

    for (int t = 0; t < TT; t++) {
        // gates partials: split-K x8  (32 x 8 = 256 blocks, kLen=192)
        sgemm128<<<dim3(NGATE / 128, 1, GSPLIT), 256>>>(
            (const float*)p_xcat, KCAT, (const float*)p_wcat, KCAT,
            (float*)p_gpart, NGATE, (size_t)BB * NGATE, KCAT / GSPLIT);
        lstm_cell<<<(BB * HH / 4) / 256, 256>>>(b_lstm);
        attn_scores<<<dim3(16, BB), 256>>>();
        attn_context<<<dim3(4, BB), 256>>>(enc, enc_len);
        // dec partials: split-K x32  (8 x 32 = 256 blocks, kLen=64)
        sgemm64<<<dim3(EMBD / 64, 1, OSPLIT), 256>>>(
            (const float*)p_hc, 2048, W_out, 2048,
            (float*)p_dpart, EMBD, (size_t)BB * EMBD, 2048 / OSPLIT);
        reduce_dec<<<(BB * EMBD / 4) / 256, 256>>>();
        // vocab logits straight into d_out[b, t, :]  (250 blocks)
        sgemm128<<<dim3(VV / 128, 1, 1), 256>>>(
            (const float*)p_dec, EMBD, W_vocab, EMBD,
            out + (size_t)t * VV, (size_t)TT * VV, 0, EMBD);
        argmax_embed<<<BB, 1024>>>(out, emb, t);
    }

    // final log-softmax in place over all B*T rows
    logsoftmax_rows<<<BB * TT, 1024>>>(out);

    // tgt_len output: always T (== 50) per the reference's final where()
    long extra = (long)out_size - (long)BB * TT * VV;
    if (extra > 0)
        fill_tail<<<(unsigned)((extra + 255) / 256), 256>>>(
            out + (size_t)BB * TT * VV, extra, 50.0f);
}